// round 1
// baseline (speedup 1.0000x reference)
#include <cuda_runtime.h>
#include <cuda_bf16.h>
#include <math.h>

// ---------------------------------------------------------------------------
// SelectiveSSM (Mamba block)
// B=2, L=1024, D_MODEL=1024, D_INNER=2048, D_STATE=16, DT_RANK=64, D_CONV=4
// ---------------------------------------------------------------------------

#define BATCH   2
#define SEQ     1024
#define DMODEL  1024
#define DINNER  2048
#define DSTATE  16
#define DTRANK  64
#define DCONV   4
#define MROWS   (BATCH * SEQ)          // 2048
#define XDBL_W  (DTRANK + 2 * DSTATE)  // 96

// -------------------- scratch (device globals; no allocation) --------------
__device__ float g_xz[MROWS * 2 * DINNER];     // [2048, 4096]  32 MB
__device__ float g_xconv[MROWS * DINNER];      // [2048, 2048]  16 MB
__device__ float g_zsilu[MROWS * DINNER];      // [2048, 2048]  16 MB
__device__ float g_xdbl[MROWS * XDBL_W];       // [2048, 96]
__device__ float g_dt[MROWS * DINNER];         // [2048, 2048]  16 MB
__device__ float g_y[MROWS * DINNER];          // [2048, 2048]  16 MB

// -------------------- generic SGEMM: C[M,N] = A[M,K] * W[N,K]^T ------------
// Both A and W are K-contiguous (row stride lda / ldw).
// EPI: 0 = none, 1 = softplus(acc + bias[n])
template<int EPI>
__global__ void gemm_atb(const float* __restrict__ A, int lda,
                         const float* __restrict__ W, int ldw,
                         const float* __restrict__ bias,
                         float* __restrict__ C, int ldc,
                         int M, int N, int K)
{
    const int BM = 64, BN = 64, BK = 16, TM = 4, TN = 4;
    __shared__ float As[BK][BM + 1];
    __shared__ float Ws[BK][BN + 1];

    const int tid = threadIdx.x;          // 256 threads
    const int tx  = tid & 15;             // 16 cols of threads
    const int ty  = tid >> 4;             // 16 rows of threads
    const int row0 = blockIdx.y * BM;
    const int col0 = blockIdx.x * BN;

    float acc[TM][TN];
#pragma unroll
    for (int i = 0; i < TM; i++)
#pragma unroll
        for (int j = 0; j < TN; j++) acc[i][j] = 0.f;

    for (int k0 = 0; k0 < K; k0 += BK) {
        // load A tile (64x16), 4 elems/thread, coalesced along K
#pragma unroll
        for (int i = tid; i < BM * BK; i += 256) {
            int r = i >> 4, kk = i & 15;
            int gr = row0 + r;
            As[kk][r] = (gr < M) ? A[(size_t)gr * lda + k0 + kk] : 0.f;
        }
#pragma unroll
        for (int i = tid; i < BN * BK; i += 256) {
            int r = i >> 4, kk = i & 15;
            int gc = col0 + r;
            Ws[kk][r] = (gc < N) ? W[(size_t)gc * ldw + k0 + kk] : 0.f;
        }
        __syncthreads();

#pragma unroll
        for (int kk = 0; kk < BK; kk++) {
            float a[TM], w[TN];
#pragma unroll
            for (int i = 0; i < TM; i++) a[i] = As[kk][ty * TM + i];
#pragma unroll
            for (int j = 0; j < TN; j++) w[j] = Ws[kk][tx * TN + j];
#pragma unroll
            for (int i = 0; i < TM; i++)
#pragma unroll
                for (int j = 0; j < TN; j++)
                    acc[i][j] = fmaf(a[i], w[j], acc[i][j]);
        }
        __syncthreads();
    }

#pragma unroll
    for (int i = 0; i < TM; i++) {
        int gr = row0 + ty * TM + i;
        if (gr >= M) continue;
#pragma unroll
        for (int j = 0; j < TN; j++) {
            int gc = col0 + tx * TN + j;
            if (gc >= N) continue;
            float v = acc[i][j];
            if (EPI == 1) {
                v += bias[gc];
                v = (v > 20.f) ? v : log1pf(__expf(v));
            }
            C[(size_t)gr * ldc + gc] = v;
        }
    }
}

// -------------------- causal depthwise conv1d + SiLU + z gate --------------
__global__ void conv_silu_kernel(const float* __restrict__ Wc,   // [DINNER,4]
                                 const float* __restrict__ bc)   // [DINNER]
{
    int i = blockIdx.x * blockDim.x + threadIdx.x;      // over MROWS*DINNER
    if (i >= MROWS * DINNER) return;
    int d = i & (DINNER - 1);
    int m = i >> 11;                                    // b*SEQ + l
    int b = m >> 10;
    int l = m & (SEQ - 1);

    float acc = bc[d];
#pragma unroll
    for (int k = 0; k < DCONV; k++) {
        int lt = l - (DCONV - 1) + k;
        if (lt >= 0)
            acc = fmaf(Wc[d * DCONV + k],
                       g_xz[(size_t)((b << 10) + lt) * (2 * DINNER) + d], acc);
    }
    g_xconv[i] = acc / (1.f + __expf(-acc));            // silu

    float zv = g_xz[(size_t)m * (2 * DINNER) + DINNER + d];
    g_zsilu[i] = zv / (1.f + __expf(-zv));
}

// -------------------- selective scan (thread per (channel, state)) ---------
// channel = b*DINNER + d (4096 channels), 16 state lanes per channel.
// Fuses skip (x_conv*D) and gate (*silu(z)) into the per-step store.
__global__ void scan_kernel(const float* __restrict__ A_log,   // [DINNER,16]
                            const float* __restrict__ Dp)      // [DINNER]
{
    int gid = blockIdx.x * blockDim.x + threadIdx.x;   // 65536
    int n  = gid & (DSTATE - 1);
    int ch = gid >> 4;                                  // 0..4095
    int b  = ch >> 11;
    int d  = ch & (DINNER - 1);

    float A  = -__expf(A_log[d * DSTATE + n]);
    float Dv = Dp[d];
    float h  = 0.f;

    for (int t = 0; t < SEQ; t++) {
        int m = b * SEQ + t;
        size_t md = (size_t)m * DINNER + d;
        float dtv = g_dt[md];
        float xv  = g_xconv[md];
        float Bv  = g_xdbl[(size_t)m * XDBL_W + DTRANK + n];
        float Cv  = g_xdbl[(size_t)m * XDBL_W + DTRANK + DSTATE + n];

        h = __expf(dtv * A) * h + dtv * Bv * xv;
        float yv = h * Cv;
        // reduce across the 16 state lanes (stays inside half-warp)
        yv += __shfl_xor_sync(0xffffffffu, yv, 1);
        yv += __shfl_xor_sync(0xffffffffu, yv, 2);
        yv += __shfl_xor_sync(0xffffffffu, yv, 4);
        yv += __shfl_xor_sync(0xffffffffu, yv, 8);
        if (n == 0)
            g_y[md] = (yv + xv * Dv) * g_zsilu[md];
    }
}

// -------------------- host launcher ----------------------------------------
extern "C" void kernel_launch(void* const* d_in, const int* in_sizes, int n_in,
                              void* d_out, int out_size)
{
    const float* x      = (const float*)d_in[0];
    const float* W_in   = (const float*)d_in[1];
    const float* W_conv = (const float*)d_in[2];
    const float* b_conv = (const float*)d_in[3];
    const float* W_x    = (const float*)d_in[4];
    const float* W_dt   = (const float*)d_in[5];
    const float* b_dt   = (const float*)d_in[6];
    const float* A_log  = (const float*)d_in[7];
    const float* Dp     = (const float*)d_in[8];
    const float* W_out  = (const float*)d_in[9];
    float* out = (float*)d_out;

    float *p_xz, *p_xconv, *p_xdbl, *p_dt, *p_y;
    cudaGetSymbolAddress((void**)&p_xz,    g_xz);
    cudaGetSymbolAddress((void**)&p_xconv, g_xconv);
    cudaGetSymbolAddress((void**)&p_xdbl,  g_xdbl);
    cudaGetSymbolAddress((void**)&p_dt,    g_dt);
    cudaGetSymbolAddress((void**)&p_y,     g_y);

    dim3 blk(256);

    // 1) xz = x @ W_in^T       [2048, 4096], K=1024
    {
        dim3 grid((2 * DINNER) / 64, MROWS / 64);
        gemm_atb<0><<<grid, blk>>>(x, DMODEL, W_in, DMODEL, nullptr,
                                   p_xz, 2 * DINNER, MROWS, 2 * DINNER, DMODEL);
    }
    // 2) causal conv + silu; silu(z)
    {
        int total = MROWS * DINNER;
        conv_silu_kernel<<<(total + 255) / 256, blk>>>(W_conv, b_conv);
    }
    // 3) x_dbl = x_conv @ W_x^T  [2048, 96], K=2048
    {
        dim3 grid((XDBL_W + 63) / 64, MROWS / 64);
        gemm_atb<0><<<grid, blk>>>(p_xconv, DINNER, W_x, DINNER, nullptr,
                                   p_xdbl, XDBL_W, MROWS, XDBL_W, DINNER);
    }
    // 4) dt = softplus(dt_low @ W_dt^T + b_dt)  [2048, 2048], K=64
    {
        dim3 grid(DINNER / 64, MROWS / 64);
        gemm_atb<1><<<grid, blk>>>(p_xdbl, XDBL_W, W_dt, DTRANK, b_dt,
                                   p_dt, DINNER, MROWS, DINNER, DTRANK);
    }
    // 5) selective scan (+ skip + gate fused)
    {
        int total = BATCH * DINNER * DSTATE;  // 65536
        scan_kernel<<<total / 256, blk>>>(A_log, Dp);
    }
    // 6) out = gated @ W_out^T  [2048, 1024], K=2048
    {
        dim3 grid(DMODEL / 64, MROWS / 64);
        gemm_atb<0><<<grid, blk>>>(p_y, DINNER, W_out, DINNER, nullptr,
                                   out, DMODEL, MROWS, DMODEL, DINNER);
    }
    (void)in_sizes; (void)n_in; (void)out_size;
}

// round 2
// speedup vs baseline: 1.5344x; 1.5344x over previous
#include <cuda_runtime.h>
#include <cuda_bf16.h>
#include <math.h>

// ---------------------------------------------------------------------------
// SelectiveSSM (Mamba block)
// B=2, L=1024, D_MODEL=1024, D_INNER=2048, D_STATE=16, DT_RANK=64, D_CONV=4
// ---------------------------------------------------------------------------

#define BATCH   2
#define SEQ     1024
#define DMODEL  1024
#define DINNER  2048
#define DSTATE  16
#define DTRANK  64
#define DCONV   4
#define MROWS   (BATCH * SEQ)          // 2048
#define XDBL_W  (DTRANK + 2 * DSTATE)  // 96

// -------------------- scratch (device globals; no allocation) --------------
__device__ float g_xz[MROWS * 2 * DINNER];     // [2048, 4096]
__device__ float g_xconv[MROWS * DINNER];      // [2048, 2048]
__device__ float g_zsilu[MROWS * DINNER];      // [2048, 2048]
__device__ float g_xdbl[MROWS * XDBL_W];       // [2048, 96]
__device__ float g_dt[MROWS * DINNER];         // [2048, 2048]
__device__ float g_y[MROWS * DINNER];          // [2048, 2048]

// ---------------------------------------------------------------------------
// Fast SGEMM: C[M,N] = A[M,K] * W[N,K]^T, both operands K-contiguous.
// Requires M%128==0, N%128==0, K%8==0, lda%4==0, ldw%4==0.
// 128x128 tile, BK=8, 256 threads, 8x8 outputs/thread (split 4+4 halves),
// double-buffered smem, float4 gmem loads, conflict-free LDS.128 reads.
// EPI: 0 = none, 1 = softplus(acc + bias[col])
// ---------------------------------------------------------------------------
template<int EPI>
__global__ __launch_bounds__(256, 2)
void gemm128(const float* __restrict__ A, int lda,
             const float* __restrict__ W, int ldw,
             const float* __restrict__ bias,
             float* __restrict__ C, int ldc, int K)
{
    __shared__ float As[2][8][128];
    __shared__ float Ws[2][8][128];

    const int tid = threadIdx.x;
    const int tx  = tid & 15;          // 16 col-groups
    const int ty  = tid >> 4;          // 16 row-groups
    const int row0 = blockIdx.y * 128;
    const int col0 = blockIdx.x * 128;

    // gmem tile loaders: one float4 per thread per operand per K-step
    const int lr = tid >> 1;           // 0..127 (tile row)
    const int ls = (tid & 1) * 4;      // k-offset 0 or 4
    const float* Aload = A + (size_t)(row0 + lr) * lda + ls;
    const float* Wload = W + (size_t)(col0 + lr) * ldw + ls;

    float4 av = *(const float4*)Aload;
    float4 wv = *(const float4*)Wload;
    As[0][ls + 0][lr] = av.x; As[0][ls + 1][lr] = av.y;
    As[0][ls + 2][lr] = av.z; As[0][ls + 3][lr] = av.w;
    Ws[0][ls + 0][lr] = wv.x; Ws[0][ls + 1][lr] = wv.y;
    Ws[0][ls + 2][lr] = wv.z; Ws[0][ls + 3][lr] = wv.w;
    __syncthreads();

    float acc[8][8];
#pragma unroll
    for (int i = 0; i < 8; i++)
#pragma unroll
        for (int j = 0; j < 8; j++) acc[i][j] = 0.f;

    int buf = 0;
    for (int k0 = 0; k0 < K; k0 += 8) {
        const bool has_next = (k0 + 8) < K;
        if (has_next) {
            av = *(const float4*)(Aload + k0 + 8);
            wv = *(const float4*)(Wload + k0 + 8);
        }
#pragma unroll
        for (int kk = 0; kk < 8; kk++) {
            float a[8], w[8];
            *(float4*)&a[0] = *(const float4*)&As[buf][kk][ty * 4];
            *(float4*)&a[4] = *(const float4*)&As[buf][kk][64 + ty * 4];
            *(float4*)&w[0] = *(const float4*)&Ws[buf][kk][tx * 4];
            *(float4*)&w[4] = *(const float4*)&Ws[buf][kk][64 + tx * 4];
#pragma unroll
            for (int i = 0; i < 8; i++)
#pragma unroll
                for (int j = 0; j < 8; j++)
                    acc[i][j] = fmaf(a[i], w[j], acc[i][j]);
        }
        if (has_next) {
            buf ^= 1;
            As[buf][ls + 0][lr] = av.x; As[buf][ls + 1][lr] = av.y;
            As[buf][ls + 2][lr] = av.z; As[buf][ls + 3][lr] = av.w;
            Ws[buf][ls + 0][lr] = wv.x; Ws[buf][ls + 1][lr] = wv.y;
            Ws[buf][ls + 2][lr] = wv.z; Ws[buf][ls + 3][lr] = wv.w;
            __syncthreads();
        }
    }

    // epilogue: 16 float4 stores per thread
#pragma unroll
    for (int hi = 0; hi < 2; hi++) {
#pragma unroll
        for (int i = 0; i < 4; i++) {
            const int gr = row0 + hi * 64 + ty * 4 + i;
            float* crow = C + (size_t)gr * ldc + col0;
#pragma unroll
            for (int hj = 0; hj < 2; hj++) {
                float v[4];
#pragma unroll
                for (int j = 0; j < 4; j++) {
                    float t = acc[hi * 4 + i][hj * 4 + j];
                    if (EPI == 1) {
                        t += bias[col0 + hj * 64 + tx * 4 + j];
                        t = (t > 20.f) ? t : log1pf(__expf(t));
                    }
                    v[j] = t;
                }
                *(float4*)(crow + hj * 64 + tx * 4) = *(float4*)v;
            }
        }
    }
}

// ---------------------------------------------------------------------------
// Fallback 64x64 SGEMM for odd shapes (GEMM2, N=96)
// ---------------------------------------------------------------------------
__global__ void gemm_atb(const float* __restrict__ A, int lda,
                         const float* __restrict__ W, int ldw,
                         float* __restrict__ C, int ldc,
                         int M, int N, int K)
{
    const int BM = 64, BN = 64, BK = 16, TM = 4, TN = 4;
    __shared__ float As[BK][BM + 1];
    __shared__ float Ws[BK][BN + 1];

    const int tid = threadIdx.x;
    const int tx  = tid & 15;
    const int ty  = tid >> 4;
    const int row0 = blockIdx.y * BM;
    const int col0 = blockIdx.x * BN;

    float acc[TM][TN];
#pragma unroll
    for (int i = 0; i < TM; i++)
#pragma unroll
        for (int j = 0; j < TN; j++) acc[i][j] = 0.f;

    for (int k0 = 0; k0 < K; k0 += BK) {
#pragma unroll
        for (int i = tid; i < BM * BK; i += 256) {
            int r = i >> 4, kk = i & 15;
            int gr = row0 + r;
            As[kk][r] = (gr < M) ? A[(size_t)gr * lda + k0 + kk] : 0.f;
        }
#pragma unroll
        for (int i = tid; i < BN * BK; i += 256) {
            int r = i >> 4, kk = i & 15;
            int gc = col0 + r;
            Ws[kk][r] = (gc < N) ? W[(size_t)gc * ldw + k0 + kk] : 0.f;
        }
        __syncthreads();

#pragma unroll
        for (int kk = 0; kk < BK; kk++) {
            float a[TM], w[TN];
#pragma unroll
            for (int i = 0; i < TM; i++) a[i] = As[kk][ty * TM + i];
#pragma unroll
            for (int j = 0; j < TN; j++) w[j] = Ws[kk][tx * TN + j];
#pragma unroll
            for (int i = 0; i < TM; i++)
#pragma unroll
                for (int j = 0; j < TN; j++)
                    acc[i][j] = fmaf(a[i], w[j], acc[i][j]);
        }
        __syncthreads();
    }

#pragma unroll
    for (int i = 0; i < TM; i++) {
        int gr = row0 + ty * TM + i;
        if (gr >= M) continue;
#pragma unroll
        for (int j = 0; j < TN; j++) {
            int gc = col0 + tx * TN + j;
            if (gc >= N) continue;
            C[(size_t)gr * ldc + gc] = acc[i][j];
        }
    }
}

// -------------------- causal depthwise conv1d + SiLU + z gate --------------
__global__ void conv_silu_kernel(const float* __restrict__ Wc,   // [DINNER,4]
                                 const float* __restrict__ bc)   // [DINNER]
{
    int i = blockIdx.x * blockDim.x + threadIdx.x;      // over MROWS*DINNER
    if (i >= MROWS * DINNER) return;
    int d = i & (DINNER - 1);
    int m = i >> 11;                                    // b*SEQ + l
    int b = m >> 10;
    int l = m & (SEQ - 1);

    float acc = bc[d];
#pragma unroll
    for (int k = 0; k < DCONV; k++) {
        int lt = l - (DCONV - 1) + k;
        if (lt >= 0)
            acc = fmaf(Wc[d * DCONV + k],
                       g_xz[(size_t)((b << 10) + lt) * (2 * DINNER) + d], acc);
    }
    g_xconv[i] = acc / (1.f + __expf(-acc));            // silu

    float zv = g_xz[(size_t)m * (2 * DINNER) + DINNER + d];
    g_zsilu[i] = zv / (1.f + __expf(-zv));
}

// -------------------- selective scan (thread per (channel, state)) ---------
__global__ void scan_kernel(const float* __restrict__ A_log,   // [DINNER,16]
                            const float* __restrict__ Dp)      // [DINNER]
{
    int gid = blockIdx.x * blockDim.x + threadIdx.x;   // 65536
    int n  = gid & (DSTATE - 1);
    int ch = gid >> 4;                                  // 0..4095
    int b  = ch >> 11;
    int d  = ch & (DINNER - 1);

    float A  = -__expf(A_log[d * DSTATE + n]);
    float Dv = Dp[d];
    float h  = 0.f;

    for (int t = 0; t < SEQ; t++) {
        int m = b * SEQ + t;
        size_t md = (size_t)m * DINNER + d;
        float dtv = g_dt[md];
        float xv  = g_xconv[md];
        float Bv  = g_xdbl[(size_t)m * XDBL_W + DTRANK + n];
        float Cv  = g_xdbl[(size_t)m * XDBL_W + DTRANK + DSTATE + n];

        h = __expf(dtv * A) * h + dtv * Bv * xv;
        float yv = h * Cv;
        yv += __shfl_xor_sync(0xffffffffu, yv, 1);
        yv += __shfl_xor_sync(0xffffffffu, yv, 2);
        yv += __shfl_xor_sync(0xffffffffu, yv, 4);
        yv += __shfl_xor_sync(0xffffffffu, yv, 8);
        if (n == 0)
            g_y[md] = (yv + xv * Dv) * g_zsilu[md];
    }
}

// -------------------- host launcher ----------------------------------------
extern "C" void kernel_launch(void* const* d_in, const int* in_sizes, int n_in,
                              void* d_out, int out_size)
{
    const float* x      = (const float*)d_in[0];
    const float* W_in   = (const float*)d_in[1];
    const float* W_conv = (const float*)d_in[2];
    const float* b_conv = (const float*)d_in[3];
    const float* W_x    = (const float*)d_in[4];
    const float* W_dt   = (const float*)d_in[5];
    const float* b_dt   = (const float*)d_in[6];
    const float* A_log  = (const float*)d_in[7];
    const float* Dp     = (const float*)d_in[8];
    const float* W_out  = (const float*)d_in[9];
    float* out = (float*)d_out;

    float *p_xz, *p_xconv, *p_xdbl, *p_dt, *p_y;
    cudaGetSymbolAddress((void**)&p_xz,    g_xz);
    cudaGetSymbolAddress((void**)&p_xconv, g_xconv);
    cudaGetSymbolAddress((void**)&p_xdbl,  g_xdbl);
    cudaGetSymbolAddress((void**)&p_dt,    g_dt);
    cudaGetSymbolAddress((void**)&p_y,     g_y);

    dim3 blk(256);

    // 1) xz = x @ W_in^T       [2048, 4096], K=1024
    {
        dim3 grid((2 * DINNER) / 128, MROWS / 128);   // 32 x 16
        gemm128<0><<<grid, blk>>>(x, DMODEL, W_in, DMODEL, nullptr,
                                  p_xz, 2 * DINNER, DMODEL);
    }
    // 2) causal conv + silu; silu(z)
    {
        int total = MROWS * DINNER;
        conv_silu_kernel<<<(total + 255) / 256, blk>>>(W_conv, b_conv);
    }
    // 3) x_dbl = x_conv @ W_x^T  [2048, 96], K=2048  (odd N -> fallback tile)
    {
        dim3 grid((XDBL_W + 63) / 64, MROWS / 64);    // 2 x 32
        gemm_atb<<<grid, blk>>>(p_xconv, DINNER, W_x, DINNER,
                                p_xdbl, XDBL_W, MROWS, XDBL_W, DINNER);
    }
    // 4) dt = softplus(x_dbl[:, :64] @ W_dt^T + b_dt)  [2048, 2048], K=64
    {
        dim3 grid(DINNER / 128, MROWS / 128);         // 16 x 16
        gemm128<1><<<grid, blk>>>(p_xdbl, XDBL_W, W_dt, DTRANK, b_dt,
                                  p_dt, DINNER, DTRANK);
    }
    // 5) selective scan (+ skip + gate fused)
    {
        int total = BATCH * DINNER * DSTATE;          // 65536
        scan_kernel<<<total / 256, blk>>>(A_log, Dp);
    }
    // 6) out = gated @ W_out^T  [2048, 1024], K=2048
    {
        dim3 grid(DMODEL / 128, MROWS / 128);         // 8 x 16
        gemm128<0><<<grid, blk>>>(p_y, DINNER, W_out, DINNER, nullptr,
                                  out, DMODEL, DINNER);
    }
    (void)in_sizes; (void)n_in; (void)out_size;
}

// round 4
// speedup vs baseline: 1.9823x; 1.2919x over previous
#include <cuda_runtime.h>
#include <cuda_bf16.h>
#include <math.h>
#include <stdint.h>

// ---------------------------------------------------------------------------
// SelectiveSSM (Mamba block) — legacy mma.sync bf16-split GEMMs (sm_100-safe)
// B=2, L=1024, D_MODEL=1024, D_INNER=2048, D_STATE=16, DT_RANK=64, D_CONV=4
// ---------------------------------------------------------------------------

#define BATCH   2
#define SEQ     1024
#define DMODEL  1024
#define DINNER  2048
#define DSTATE  16
#define DTRANK  64
#define DCONV   4
#define MROWS   (BATCH * SEQ)          // 2048
#define XDBL_W  (DTRANK + 2 * DSTATE)  // 96

// -------------------- scratch (device globals; no allocation) --------------
__device__ float g_xz[MROWS * 2 * DINNER];     // [2048, 4096]
__device__ float g_xconv[MROWS * DINNER];      // [2048, 2048]
__device__ float g_zsilu[MROWS * DINNER];      // [2048, 2048]
__device__ float g_xdbl[MROWS * XDBL_W];       // [2048, 96]
__device__ float g_dt[MROWS * DINNER];         // [2048, 2048]
__device__ float g_y[MROWS * DINNER];          // [2048, 2048]

// ===================== warp-MMA helpers (sm_80+ PTX only) ==================
__device__ __forceinline__ uint32_t smem_u32(const void* p) {
    uint32_t a;
    asm("{ .reg .u64 t; cvta.to.shared.u64 t, %1; cvt.u32.u64 %0, t; }"
        : "=r"(a) : "l"(p));
    return a;
}

__device__ __forceinline__ void ldsm_x4(uint32_t* r, uint32_t addr) {
    asm volatile("ldmatrix.sync.aligned.m8n8.x4.shared.b16 {%0,%1,%2,%3}, [%4];"
        : "=r"(r[0]), "=r"(r[1]), "=r"(r[2]), "=r"(r[3]) : "r"(addr));
}
__device__ __forceinline__ void ldsm_x2(uint32_t* r, uint32_t addr) {
    asm volatile("ldmatrix.sync.aligned.m8n8.x2.shared.b16 {%0,%1}, [%2];"
        : "=r"(r[0]), "=r"(r[1]) : "r"(addr));
}
__device__ __forceinline__ void mma16816(float* c, const uint32_t* a,
                                         const uint32_t* b) {
    asm volatile("mma.sync.aligned.m16n8k16.row.col.f32.bf16.bf16.f32 "
        "{%0,%1,%2,%3}, {%4,%5,%6,%7}, {%8,%9}, {%0,%1,%2,%3};"
        : "+f"(c[0]), "+f"(c[1]), "+f"(c[2]), "+f"(c[3])
        : "r"(a[0]), "r"(a[1]), "r"(a[2]), "r"(a[3]), "r"(b[0]), "r"(b[1]));
}

// ---------------------------------------------------------------------------
// Tensor-core GEMM: C[M,N] = A[M,K] * W[N,K]^T, fp32 in/out.
// bf16 hi/lo split (3 MMA terms) for ~fp32 accuracy.
// CTA tile 128x64, BK=32, 256 threads (8 warps: 4m x 2n, warptile 32x32).
// Requires M%128==0, N%64==0, K%32==0, lda%4==0, ldw%4==0.
// EPI: 0 = none, 1 = softplus(acc + bias[col])
// ---------------------------------------------------------------------------
#define BMT   128
#define BNT   64
#define BKT   32
#define PITCH 40     // bf16 elems per smem row (80B: conflict-free ldmatrix)

template<int EPI>
__global__ __launch_bounds__(256, 2)
void gemm_mma(const float* __restrict__ A, int lda,
              const float* __restrict__ W, int ldw,
              const float* __restrict__ bias,
              float* __restrict__ C, int ldc, int K)
{
    __shared__ alignas(16) uint16_t sAh[BMT * PITCH];
    __shared__ alignas(16) uint16_t sAl[BMT * PITCH];
    __shared__ alignas(16) uint16_t sBh[BNT * PITCH];
    __shared__ alignas(16) uint16_t sBl[BNT * PITCH];

    const int tid  = threadIdx.x;
    const int lane = tid & 31;
    const int wid  = tid >> 5;
    const int wm   = wid >> 1;           // 0..3  (m)
    const int wn   = wid & 1;            // 0..1  (n)
    const int row0 = blockIdx.y * BMT;
    const int col0 = blockIdx.x * BNT;

    const uint32_t uAh = smem_u32(sAh), uAl = smem_u32(sAl);
    const uint32_t uBh = smem_u32(sBh), uBl = smem_u32(sBl);

    // ldmatrix per-lane offsets (elements)
    const int a_r = lane & 15, a_k = (lane >> 4) << 3;
    const int b_r = lane & 7,  b_k = ((lane >> 3) & 1) << 3;

    float acc[2][4][4];
#pragma unroll
    for (int mi = 0; mi < 2; mi++)
#pragma unroll
        for (int ni = 0; ni < 4; ni++)
#pragma unroll
            for (int j = 0; j < 4; j++) acc[mi][ni][j] = 0.f;

    for (int k0 = 0; k0 < K; k0 += BKT) {
        if (k0) __syncthreads();
        // ---- A tile: 128x32 fp32 -> hi/lo bf16 (4 float4 per thread) ----
#pragma unroll
        for (int it = 0; it < 4; it++) {
            int idx = it * 256 + tid;
            int r = idx >> 3, c4 = (idx & 7) << 2;
            float4 v = *(const float4*)(A + (size_t)(row0 + r) * lda + k0 + c4);
            float f[4] = {v.x, v.y, v.z, v.w};
#pragma unroll
            for (int j = 0; j < 4; j += 2) {
                __nv_bfloat16 h0 = __float2bfloat16(f[j]);
                __nv_bfloat16 h1 = __float2bfloat16(f[j + 1]);
                __nv_bfloat16 l0 = __float2bfloat16(f[j]     - __bfloat162float(h0));
                __nv_bfloat16 l1 = __float2bfloat16(f[j + 1] - __bfloat162float(h1));
                int e = r * PITCH + c4 + j;
                *(__nv_bfloat162*)&sAh[e] = __nv_bfloat162(h0, h1);
                *(__nv_bfloat162*)&sAl[e] = __nv_bfloat162(l0, l1);
            }
        }
        // ---- B tile: 64x32 fp32 -> hi/lo bf16 (2 float4 per thread) ----
#pragma unroll
        for (int it = 0; it < 2; it++) {
            int idx = it * 256 + tid;
            int r = idx >> 3, c4 = (idx & 7) << 2;
            float4 v = *(const float4*)(W + (size_t)(col0 + r) * ldw + k0 + c4);
            float f[4] = {v.x, v.y, v.z, v.w};
#pragma unroll
            for (int j = 0; j < 4; j += 2) {
                __nv_bfloat16 h0 = __float2bfloat16(f[j]);
                __nv_bfloat16 h1 = __float2bfloat16(f[j + 1]);
                __nv_bfloat16 l0 = __float2bfloat16(f[j]     - __bfloat162float(h0));
                __nv_bfloat16 l1 = __float2bfloat16(f[j + 1] - __bfloat162float(h1));
                int e = r * PITCH + c4 + j;
                *(__nv_bfloat162*)&sBh[e] = __nv_bfloat162(h0, h1);
                *(__nv_bfloat162*)&sBl[e] = __nv_bfloat162(l0, l1);
            }
        }
        __syncthreads();

        // ---- 2 k16 steps ----
#pragma unroll
        for (int s = 0; s < 2; s++) {
            uint32_t ah[2][4], al[2][4], bh[4][2], bl[4][2];
#pragma unroll
            for (int mi = 0; mi < 2; mi++) {
                int e = (wm * 32 + mi * 16 + a_r) * PITCH + s * 16 + a_k;
                ldsm_x4(ah[mi], uAh + (uint32_t)e * 2);
                ldsm_x4(al[mi], uAl + (uint32_t)e * 2);
            }
#pragma unroll
            for (int ni = 0; ni < 4; ni++) {
                int e = (wn * 32 + ni * 8 + b_r) * PITCH + s * 16 + b_k;
                ldsm_x2(bh[ni], uBh + (uint32_t)e * 2);
                ldsm_x2(bl[ni], uBl + (uint32_t)e * 2);
            }
#pragma unroll
            for (int mi = 0; mi < 2; mi++)
#pragma unroll
                for (int ni = 0; ni < 4; ni++) {
                    mma16816(acc[mi][ni], ah[mi], bh[ni]);
                    mma16816(acc[mi][ni], ah[mi], bl[ni]);
                    mma16816(acc[mi][ni], al[mi], bh[ni]);
                }
        }
    }

    // ---- epilogue ----
    const int cr = lane >> 2;            // 0..7
    const int cc = (lane & 3) * 2;       // 0,2,4,6
#pragma unroll
    for (int mi = 0; mi < 2; mi++) {
#pragma unroll
        for (int ni = 0; ni < 4; ni++) {
            int row = row0 + wm * 32 + mi * 16 + cr;
            int col = col0 + wn * 32 + ni * 8 + cc;
            float v[4] = {acc[mi][ni][0], acc[mi][ni][1],
                          acc[mi][ni][2], acc[mi][ni][3]};
            if (EPI == 1) {
#pragma unroll
                for (int j = 0; j < 4; j++) {
                    float t = v[j] + bias[col + (j & 1)];
                    v[j] = (t > 20.f) ? t : log1pf(__expf(t));
                }
            }
            *(float2*)(C + (size_t)row * ldc + col)       = make_float2(v[0], v[1]);
            *(float2*)(C + (size_t)(row + 8) * ldc + col) = make_float2(v[2], v[3]);
        }
    }
}

// ---------------------------------------------------------------------------
// Fallback 64x64 SGEMM for odd shapes (GEMM2, N=96)
// ---------------------------------------------------------------------------
__global__ void gemm_atb(const float* __restrict__ A, int lda,
                         const float* __restrict__ W, int ldw,
                         float* __restrict__ C, int ldc,
                         int M, int N, int K)
{
    const int BM = 64, BN = 64, BK = 16, TM = 4, TN = 4;
    __shared__ float As[BK][BM + 1];
    __shared__ float Ws[BK][BN + 1];

    const int tid = threadIdx.x;
    const int tx  = tid & 15;
    const int ty  = tid >> 4;
    const int row0 = blockIdx.y * BM;
    const int col0 = blockIdx.x * BN;

    float acc[TM][TN];
#pragma unroll
    for (int i = 0; i < TM; i++)
#pragma unroll
        for (int j = 0; j < TN; j++) acc[i][j] = 0.f;

    for (int k0 = 0; k0 < K; k0 += BK) {
#pragma unroll
        for (int i = tid; i < BM * BK; i += 256) {
            int r = i >> 4, kk = i & 15;
            int gr = row0 + r;
            As[kk][r] = (gr < M) ? A[(size_t)gr * lda + k0 + kk] : 0.f;
        }
#pragma unroll
        for (int i = tid; i < BN * BK; i += 256) {
            int r = i >> 4, kk = i & 15;
            int gc = col0 + r;
            Ws[kk][r] = (gc < N) ? W[(size_t)gc * ldw + k0 + kk] : 0.f;
        }
        __syncthreads();

#pragma unroll
        for (int kk = 0; kk < BK; kk++) {
            float a[TM], w[TN];
#pragma unroll
            for (int i = 0; i < TM; i++) a[i] = As[kk][ty * TM + i];
#pragma unroll
            for (int j = 0; j < TN; j++) w[j] = Ws[kk][tx * TN + j];
#pragma unroll
            for (int i = 0; i < TM; i++)
#pragma unroll
                for (int j = 0; j < TN; j++)
                    acc[i][j] = fmaf(a[i], w[j], acc[i][j]);
        }
        __syncthreads();
    }

#pragma unroll
    for (int i = 0; i < TM; i++) {
        int gr = row0 + ty * TM + i;
        if (gr >= M) continue;
#pragma unroll
        for (int j = 0; j < TN; j++) {
            int gc = col0 + tx * TN + j;
            if (gc >= N) continue;
            C[(size_t)gr * ldc + gc] = acc[i][j];
        }
    }
}

// -------------------- causal depthwise conv1d + SiLU + z gate --------------
__global__ void conv_silu_kernel(const float* __restrict__ Wc,   // [DINNER,4]
                                 const float* __restrict__ bc)   // [DINNER]
{
    int i = blockIdx.x * blockDim.x + threadIdx.x;      // over MROWS*DINNER
    if (i >= MROWS * DINNER) return;
    int d = i & (DINNER - 1);
    int m = i >> 11;                                    // b*SEQ + l
    int b = m >> 10;
    int l = m & (SEQ - 1);

    float acc = bc[d];
#pragma unroll
    for (int k = 0; k < DCONV; k++) {
        int lt = l - (DCONV - 1) + k;
        if (lt >= 0)
            acc = fmaf(Wc[d * DCONV + k],
                       g_xz[(size_t)((b << 10) + lt) * (2 * DINNER) + d], acc);
    }
    g_xconv[i] = acc / (1.f + __expf(-acc));            // silu

    float zv = g_xz[(size_t)m * (2 * DINNER) + DINNER + d];
    g_zsilu[i] = zv / (1.f + __expf(-zv));
}

// -------------------- selective scan (thread per (channel, state)) ---------
__global__ void scan_kernel(const float* __restrict__ A_log,   // [DINNER,16]
                            const float* __restrict__ Dp)      // [DINNER]
{
    int gid = blockIdx.x * blockDim.x + threadIdx.x;   // 65536
    int n  = gid & (DSTATE - 1);
    int ch = gid >> 4;                                  // 0..4095
    int b  = ch >> 11;
    int d  = ch & (DINNER - 1);

    float A  = -__expf(A_log[d * DSTATE + n]);
    float Dv = Dp[d];
    float h  = 0.f;

    for (int t = 0; t < SEQ; t++) {
        int m = b * SEQ + t;
        size_t md = (size_t)m * DINNER + d;
        float dtv = g_dt[md];
        float xv  = g_xconv[md];
        float Bv  = g_xdbl[(size_t)m * XDBL_W + DTRANK + n];
        float Cv  = g_xdbl[(size_t)m * XDBL_W + DTRANK + DSTATE + n];

        h = __expf(dtv * A) * h + dtv * Bv * xv;
        float yv = h * Cv;
        yv += __shfl_xor_sync(0xffffffffu, yv, 1);
        yv += __shfl_xor_sync(0xffffffffu, yv, 2);
        yv += __shfl_xor_sync(0xffffffffu, yv, 4);
        yv += __shfl_xor_sync(0xffffffffu, yv, 8);
        if (n == 0)
            g_y[md] = (yv + xv * Dv) * g_zsilu[md];
    }
}

// -------------------- host launcher ----------------------------------------
extern "C" void kernel_launch(void* const* d_in, const int* in_sizes, int n_in,
                              void* d_out, int out_size)
{
    const float* x      = (const float*)d_in[0];
    const float* W_in   = (const float*)d_in[1];
    const float* W_conv = (const float*)d_in[2];
    const float* b_conv = (const float*)d_in[3];
    const float* W_x    = (const float*)d_in[4];
    const float* W_dt   = (const float*)d_in[5];
    const float* b_dt   = (const float*)d_in[6];
    const float* A_log  = (const float*)d_in[7];
    const float* Dp     = (const float*)d_in[8];
    const float* W_out  = (const float*)d_in[9];
    float* out = (float*)d_out;

    float *p_xz, *p_xconv, *p_xdbl, *p_dt, *p_y;
    cudaGetSymbolAddress((void**)&p_xz,    g_xz);
    cudaGetSymbolAddress((void**)&p_xconv, g_xconv);
    cudaGetSymbolAddress((void**)&p_xdbl,  g_xdbl);
    cudaGetSymbolAddress((void**)&p_dt,    g_dt);
    cudaGetSymbolAddress((void**)&p_y,     g_y);

    // 1) xz = x @ W_in^T       [2048, 4096], K=1024
    {
        dim3 grid((2 * DINNER) / BNT, MROWS / BMT);   // 64 x 16
        gemm_mma<0><<<grid, 256>>>(x, DMODEL, W_in, DMODEL, nullptr,
                                   p_xz, 2 * DINNER, DMODEL);
    }
    // 2) causal conv + silu; silu(z)
    {
        int total = MROWS * DINNER;
        conv_silu_kernel<<<(total + 255) / 256, 256>>>(W_conv, b_conv);
    }
    // 3) x_dbl = x_conv @ W_x^T  [2048, 96], K=2048  (odd N -> fallback tile)
    {
        dim3 grid((XDBL_W + 63) / 64, MROWS / 64);    // 2 x 32
        gemm_atb<<<grid, 256>>>(p_xconv, DINNER, W_x, DINNER,
                                p_xdbl, XDBL_W, MROWS, XDBL_W, DINNER);
    }
    // 4) dt = softplus(x_dbl[:, :64] @ W_dt^T + b_dt)  [2048, 2048], K=64
    {
        dim3 grid(DINNER / BNT, MROWS / BMT);         // 32 x 16
        gemm_mma<1><<<grid, 256>>>(p_xdbl, XDBL_W, W_dt, DTRANK, b_dt,
                                   p_dt, DINNER, DTRANK);
    }
    // 5) selective scan (+ skip + gate fused)
    {
        int total = BATCH * DINNER * DSTATE;          // 65536
        scan_kernel<<<total / 256, 256>>>(A_log, Dp);
    }
    // 6) out = gated @ W_out^T  [2048, 1024], K=2048
    {
        dim3 grid(DMODEL / BNT, MROWS / BMT);         // 16 x 16
        gemm_mma<0><<<grid, 256>>>(p_y, DINNER, W_out, DINNER, nullptr,
                                   out, DMODEL, DINNER);
    }
    (void)in_sizes; (void)n_in; (void)out_size;
}

// round 6
// speedup vs baseline: 2.3506x; 1.1858x over previous
#include <cuda_runtime.h>
#include <cuda_bf16.h>
#include <math.h>
#include <stdint.h>

// ---------------------------------------------------------------------------
// SelectiveSSM (Mamba block) — pre-split bf16 hi/lo operands + cp.async
// double-buffered mma.sync GEMMs (sm_100-safe PTX only).
// B=2, L=1024, D_MODEL=1024, D_INNER=2048, D_STATE=16, DT_RANK=64, D_CONV=4
// ---------------------------------------------------------------------------

#define BATCH   2
#define SEQ     1024
#define DMODEL  1024
#define DINNER  2048
#define DSTATE  16
#define DTRANK  64
#define DCONV   4
#define MROWS   (BATCH * SEQ)          // 2048
#define XPITCH  128                    // padded x_dbl width (logical 96)

// -------------------- fp32 scratch -----------------------------------------
__device__ float g_xz[MROWS * 2 * DINNER];     // [2048, 4096]
__device__ float g_xconv[MROWS * DINNER];      // [2048, 2048]
__device__ float g_zsilu[MROWS * DINNER];      // [2048, 2048]
__device__ float g_xdbl[MROWS * XPITCH];       // [2048, 128] (cols 96.. = 0)
__device__ float g_dt[MROWS * DINNER];         // [2048, 2048]
__device__ float g_y[MROWS * DINNER];          // [2048, 2048]

// -------------------- bf16 hi/lo planes ------------------------------------
__device__ __nv_bfloat16 g_xhi[MROWS * DMODEL],   g_xlo[MROWS * DMODEL];
__device__ __nv_bfloat16 g_Wih[2 * DINNER * DMODEL], g_Wil[2 * DINNER * DMODEL];
__device__ __nv_bfloat16 g_xch[MROWS * DINNER],   g_xcl[MROWS * DINNER];
__device__ __nv_bfloat16 g_Wxh[XPITCH * DINNER],  g_Wxl[XPITCH * DINNER];
__device__ __nv_bfloat16 g_xdh[MROWS * XPITCH],   g_xdl[MROWS * XPITCH];
__device__ __nv_bfloat16 g_Wdh[DINNER * DTRANK],  g_Wdl[DINNER * DTRANK];
__device__ __nv_bfloat16 g_yh[MROWS * DINNER],    g_yl[MROWS * DINNER];
__device__ __nv_bfloat16 g_Woh[DMODEL * DINNER],  g_Wol[DMODEL * DINNER];

// ===================== PTX helpers (sm_80+ only) ===========================
__device__ __forceinline__ uint32_t smem_u32(const void* p) {
    uint32_t a;
    asm("{ .reg .u64 t; cvta.to.shared.u64 t, %1; cvt.u32.u64 %0, t; }"
        : "=r"(a) : "l"(p));
    return a;
}
__device__ __forceinline__ void ldsm_x4(uint32_t* r, uint32_t addr) {
    asm volatile("ldmatrix.sync.aligned.m8n8.x4.shared.b16 {%0,%1,%2,%3}, [%4];"
        : "=r"(r[0]), "=r"(r[1]), "=r"(r[2]), "=r"(r[3]) : "r"(addr));
}
__device__ __forceinline__ void ldsm_x2(uint32_t* r, uint32_t addr) {
    asm volatile("ldmatrix.sync.aligned.m8n8.x2.shared.b16 {%0,%1}, [%2];"
        : "=r"(r[0]), "=r"(r[1]) : "r"(addr));
}
__device__ __forceinline__ void mma16816(float* c, const uint32_t* a,
                                         const uint32_t* b) {
    asm volatile("mma.sync.aligned.m16n8k16.row.col.f32.bf16.bf16.f32 "
        "{%0,%1,%2,%3}, {%4,%5,%6,%7}, {%8,%9}, {%0,%1,%2,%3};"
        : "+f"(c[0]), "+f"(c[1]), "+f"(c[2]), "+f"(c[3])
        : "r"(a[0]), "r"(a[1]), "r"(a[2]), "r"(a[3]), "r"(b[0]), "r"(b[1]));
}
#define CPA16(dst, src) \
    asm volatile("cp.async.cg.shared.global [%0], [%1], 16;" \
                 :: "r"(dst), "l"(src) : "memory")
#define CP_COMMIT() asm volatile("cp.async.commit_group;" ::: "memory")

// ---------------------------------------------------------------------------
// Tensor-core GEMM on pre-split operands:
//   C[M,N] = (Ahi+Alo)[M,K] * (Whi+Wlo)[N,K]^T   (3-term Markidis split)
// CTA tile 128x64, BK=32, 256 threads (8 warps: 4m x 2n, warptile 32x32).
// Double-buffered smem filled by cp.async. PITCH=40 (80B rows, 16B aligned).
// Requires M%128==0, N%64==0, K%32==0, lda%8==0, ldw%8==0.
// EPI: 0 = none, 1 = softplus(acc + bias[col])
// ---------------------------------------------------------------------------
#define BMT   128
#define BNT   64
#define BKT   32
#define PITCH 40
#define A_PLANE 10240u   // 128*40*2 bytes
#define B_PLANE 5120u    // 64*40*2 bytes
#define GSMEM   61440    // 2 bufs * 2 planes * (A_PLANE + B_PLANE)

// Tile rows are 32 bf16 = 64 B = 4 x 16B chunks (ch = 0..3).
// A plane: 128 rows * 4 chunks = 512 chunk-loads -> 2 iters of 256 threads.
// B plane:  64 rows * 4 chunks = 256 chunk-loads -> 1 iter.
__device__ __forceinline__ void cpa_fill(
    uint32_t sAh, uint32_t sAl, uint32_t sBh, uint32_t sBl,
    const __nv_bfloat16* Ahi, const __nv_bfloat16* Alo, int lda,
    const __nv_bfloat16* Whi, const __nv_bfloat16* Wlo, int ldw,
    int row0, int col0, int k0, int tid)
{
#pragma unroll
    for (int it = 0; it < 2; it++) {
        int idx = it * 256 + tid;
        int r = idx >> 2, ch = idx & 3;
        const size_t aoff = (size_t)(row0 + r) * lda + k0 + ch * 8;
        const uint32_t sd = (uint32_t)(r * 80 + ch * 16);
        CPA16(sAh + sd, Ahi + aoff);
        CPA16(sAl + sd, Alo + aoff);
    }
    {
        int r = tid >> 2, ch = tid & 3;
        const size_t boff = (size_t)(col0 + r) * ldw + k0 + ch * 8;
        const uint32_t sd = (uint32_t)(r * 80 + ch * 16);
        CPA16(sBh + sd, Whi + boff);
        CPA16(sBl + sd, Wlo + boff);
    }
    CP_COMMIT();
}

template<int EPI>
__global__ __launch_bounds__(256, 2)
void gemm_mma(const __nv_bfloat16* __restrict__ Ahi,
              const __nv_bfloat16* __restrict__ Alo, int lda,
              const __nv_bfloat16* __restrict__ Whi,
              const __nv_bfloat16* __restrict__ Wlo, int ldw,
              const float* __restrict__ bias,
              float* __restrict__ C, int ldc, int K)
{
    extern __shared__ char smem[];
    const uint32_t sb = smem_u32(smem);
    // layout: [buf][plane] A then B
    const uint32_t aB[2][2] = {{sb, sb + A_PLANE},
                               {sb + 2 * A_PLANE, sb + 3 * A_PLANE}};
    const uint32_t bB[2][2] = {{sb + 4 * A_PLANE, sb + 4 * A_PLANE + B_PLANE},
                               {sb + 4 * A_PLANE + 2 * B_PLANE,
                                sb + 4 * A_PLANE + 3 * B_PLANE}};

    const int tid  = threadIdx.x;
    const int lane = tid & 31;
    const int wid  = tid >> 5;
    const int wm   = wid >> 1;           // 0..3
    const int wn   = wid & 1;            // 0..1
    const int row0 = blockIdx.y * BMT;
    const int col0 = blockIdx.x * BNT;

    const int a_r = lane & 15, a_k = (lane >> 4) << 3;
    const int b_r = lane & 7,  b_k = ((lane >> 3) & 1) << 3;

    float acc[2][4][4];
#pragma unroll
    for (int mi = 0; mi < 2; mi++)
#pragma unroll
        for (int ni = 0; ni < 4; ni++)
#pragma unroll
            for (int j = 0; j < 4; j++) acc[mi][ni][j] = 0.f;

    const int nit = K / BKT;
    cpa_fill(aB[0][0], aB[0][1], bB[0][0], bB[0][1],
             Ahi, Alo, lda, Whi, Wlo, ldw, row0, col0, 0, tid);

    for (int c = 0; c < nit; c++) {
        const int cur = c & 1;
        if (c + 1 < nit) {
            cpa_fill(aB[cur ^ 1][0], aB[cur ^ 1][1], bB[cur ^ 1][0], bB[cur ^ 1][1],
                     Ahi, Alo, lda, Whi, Wlo, ldw, row0, col0, (c + 1) * BKT, tid);
            asm volatile("cp.async.wait_group 1;" ::: "memory");
        } else {
            asm volatile("cp.async.wait_group 0;" ::: "memory");
        }
        __syncthreads();

#pragma unroll
        for (int s = 0; s < 2; s++) {
            uint32_t ah[2][4], al[2][4], bh[4][2], bl[4][2];
#pragma unroll
            for (int mi = 0; mi < 2; mi++) {
                uint32_t e = (uint32_t)((wm * 32 + mi * 16 + a_r) * PITCH
                                        + s * 16 + a_k) * 2u;
                ldsm_x4(ah[mi], aB[cur][0] + e);
                ldsm_x4(al[mi], aB[cur][1] + e);
            }
#pragma unroll
            for (int ni = 0; ni < 4; ni++) {
                uint32_t e = (uint32_t)((wn * 32 + ni * 8 + b_r) * PITCH
                                        + s * 16 + b_k) * 2u;
                ldsm_x2(bh[ni], bB[cur][0] + e);
                ldsm_x2(bl[ni], bB[cur][1] + e);
            }
#pragma unroll
            for (int mi = 0; mi < 2; mi++)
#pragma unroll
                for (int ni = 0; ni < 4; ni++) {
                    mma16816(acc[mi][ni], ah[mi], bh[ni]);
                    mma16816(acc[mi][ni], ah[mi], bl[ni]);
                    mma16816(acc[mi][ni], al[mi], bh[ni]);
                }
        }
        __syncthreads();
    }

    // ---- epilogue ----
    const int cr = lane >> 2;
    const int cc = (lane & 3) * 2;
#pragma unroll
    for (int mi = 0; mi < 2; mi++) {
#pragma unroll
        for (int ni = 0; ni < 4; ni++) {
            int row = row0 + wm * 32 + mi * 16 + cr;
            int col = col0 + wn * 32 + ni * 8 + cc;
            float v[4] = {acc[mi][ni][0], acc[mi][ni][1],
                          acc[mi][ni][2], acc[mi][ni][3]};
            if (EPI == 1) {
#pragma unroll
                for (int j = 0; j < 4; j++) {
                    float t = v[j] + bias[col + (j & 1)];
                    v[j] = (t > 20.f) ? t : log1pf(__expf(t));
                }
            }
            *(float2*)(C + (size_t)row * ldc + col)       = make_float2(v[0], v[1]);
            *(float2*)(C + (size_t)(row + 8) * ldc + col) = make_float2(v[2], v[3]);
        }
    }
}

// -------------------- fp32 -> bf16 hi/lo converters ------------------------
__global__ void cvt_hl(const float4* __restrict__ in,
                       __nv_bfloat162* __restrict__ hi,
                       __nv_bfloat162* __restrict__ lo, int n4)
{
    int i = blockIdx.x * blockDim.x + threadIdx.x;
    if (i >= n4) return;
    float4 v = in[i];
    float f[4] = {v.x, v.y, v.z, v.w};
    __nv_bfloat16 h[4], l[4];
#pragma unroll
    for (int j = 0; j < 4; j++) {
        h[j] = __float2bfloat16(f[j]);
        l[j] = __float2bfloat16(f[j] - __bfloat162float(h[j]));
    }
    hi[2 * i]     = __nv_bfloat162(h[0], h[1]);
    hi[2 * i + 1] = __nv_bfloat162(h[2], h[3]);
    lo[2 * i]     = __nv_bfloat162(l[0], l[1]);
    lo[2 * i + 1] = __nv_bfloat162(l[2], l[3]);
}

// W_x [96, 2048] -> padded [128, 2048] hi/lo (rows 96..127 zero)
__global__ void cvt_hl_pad_wx(const float* __restrict__ in,
                              __nv_bfloat162* __restrict__ hi,
                              __nv_bfloat162* __restrict__ lo)
{
    int i = blockIdx.x * blockDim.x + threadIdx.x;   // over 128*2048/4
    if (i >= XPITCH * DINNER / 4) return;
    int row = i >> 9;                 // /(2048/4)
    int col4 = (i & 511) << 2;
    float f[4] = {0.f, 0.f, 0.f, 0.f};
    if (row < 96) {
        float4 v = *(const float4*)(in + (size_t)row * DINNER + col4);
        f[0] = v.x; f[1] = v.y; f[2] = v.z; f[3] = v.w;
    }
    __nv_bfloat16 h[4], l[4];
#pragma unroll
    for (int j = 0; j < 4; j++) {
        h[j] = __float2bfloat16(f[j]);
        l[j] = __float2bfloat16(f[j] - __bfloat162float(h[j]));
    }
    hi[2 * i]     = __nv_bfloat162(h[0], h[1]);
    hi[2 * i + 1] = __nv_bfloat162(h[2], h[3]);
    lo[2 * i]     = __nv_bfloat162(l[0], l[1]);
    lo[2 * i + 1] = __nv_bfloat162(l[2], l[3]);
}

// -------------------- causal depthwise conv1d + SiLU + z gate --------------
__global__ void conv_silu_kernel(const float* __restrict__ Wc,   // [DINNER,4]
                                 const float* __restrict__ bc)   // [DINNER]
{
    int i = blockIdx.x * blockDim.x + threadIdx.x;      // over MROWS*DINNER
    if (i >= MROWS * DINNER) return;
    int d = i & (DINNER - 1);
    int m = i >> 11;                                    // b*SEQ + l
    int b = m >> 10;
    int l = m & (SEQ - 1);

    float acc = bc[d];
#pragma unroll
    for (int k = 0; k < DCONV; k++) {
        int lt = l - (DCONV - 1) + k;
        if (lt >= 0)
            acc = fmaf(Wc[d * DCONV + k],
                       g_xz[(size_t)((b << 10) + lt) * (2 * DINNER) + d], acc);
    }
    g_xconv[i] = acc / (1.f + __expf(-acc));            // silu

    float zv = g_xz[(size_t)m * (2 * DINNER) + DINNER + d];
    g_zsilu[i] = zv / (1.f + __expf(-zv));
}

// -------------------- selective scan (thread per (channel, state)) ---------
__global__ void scan_kernel(const float* __restrict__ A_log,   // [DINNER,16]
                            const float* __restrict__ Dp)      // [DINNER]
{
    int gid = blockIdx.x * blockDim.x + threadIdx.x;   // 65536
    int n  = gid & (DSTATE - 1);
    int ch = gid >> 4;                                  // 0..4095
    int b  = ch >> 11;
    int d  = ch & (DINNER - 1);

    float A  = -__expf(A_log[d * DSTATE + n]);
    float Dv = Dp[d];
    float h  = 0.f;

    for (int t = 0; t < SEQ; t++) {
        int m = b * SEQ + t;
        size_t md = (size_t)m * DINNER + d;
        float dtv = g_dt[md];
        float xv  = g_xconv[md];
        float Bv  = g_xdbl[(size_t)m * XPITCH + DTRANK + n];
        float Cv  = g_xdbl[(size_t)m * XPITCH + DTRANK + DSTATE + n];

        h = __expf(dtv * A) * h + dtv * Bv * xv;
        float yv = h * Cv;
        yv += __shfl_xor_sync(0xffffffffu, yv, 1);
        yv += __shfl_xor_sync(0xffffffffu, yv, 2);
        yv += __shfl_xor_sync(0xffffffffu, yv, 4);
        yv += __shfl_xor_sync(0xffffffffu, yv, 8);
        if (n == 0)
            g_y[md] = (yv + xv * Dv) * g_zsilu[md];
    }
}

// -------------------- host launcher ----------------------------------------
extern "C" void kernel_launch(void* const* d_in, const int* in_sizes, int n_in,
                              void* d_out, int out_size)
{
    const float* x      = (const float*)d_in[0];
    const float* W_in   = (const float*)d_in[1];
    const float* W_conv = (const float*)d_in[2];
    const float* b_conv = (const float*)d_in[3];
    const float* W_x    = (const float*)d_in[4];
    const float* W_dt   = (const float*)d_in[5];
    const float* b_dt   = (const float*)d_in[6];
    const float* A_log  = (const float*)d_in[7];
    const float* Dp     = (const float*)d_in[8];
    const float* W_out  = (const float*)d_in[9];
    float* out = (float*)d_out;

    float *p_xz, *p_xconv, *p_xdbl, *p_dt, *p_y;
    cudaGetSymbolAddress((void**)&p_xz,    g_xz);
    cudaGetSymbolAddress((void**)&p_xconv, g_xconv);
    cudaGetSymbolAddress((void**)&p_xdbl,  g_xdbl);
    cudaGetSymbolAddress((void**)&p_dt,    g_dt);
    cudaGetSymbolAddress((void**)&p_y,     g_y);

    __nv_bfloat16 *xhi, *xlo, *Wih, *Wil, *xch, *xcl, *Wxh, *Wxl;
    __nv_bfloat16 *xdh, *xdl, *Wdh, *Wdl, *yh, *yl, *Woh, *Wol;
    cudaGetSymbolAddress((void**)&xhi, g_xhi); cudaGetSymbolAddress((void**)&xlo, g_xlo);
    cudaGetSymbolAddress((void**)&Wih, g_Wih); cudaGetSymbolAddress((void**)&Wil, g_Wil);
    cudaGetSymbolAddress((void**)&xch, g_xch); cudaGetSymbolAddress((void**)&xcl, g_xcl);
    cudaGetSymbolAddress((void**)&Wxh, g_Wxh); cudaGetSymbolAddress((void**)&Wxl, g_Wxl);
    cudaGetSymbolAddress((void**)&xdh, g_xdh); cudaGetSymbolAddress((void**)&xdl, g_xdl);
    cudaGetSymbolAddress((void**)&Wdh, g_Wdh); cudaGetSymbolAddress((void**)&Wdl, g_Wdl);
    cudaGetSymbolAddress((void**)&yh,  g_yh);  cudaGetSymbolAddress((void**)&yl,  g_yl);
    cudaGetSymbolAddress((void**)&Woh, g_Woh); cudaGetSymbolAddress((void**)&Wol, g_Wol);

    cudaFuncSetAttribute(gemm_mma<0>, cudaFuncAttributeMaxDynamicSharedMemorySize, GSMEM);
    cudaFuncSetAttribute(gemm_mma<1>, cudaFuncAttributeMaxDynamicSharedMemorySize, GSMEM);

    const int CT = 256;
    #define CVT(src, dh, dl, n) \
        cvt_hl<<<((n) / 4 + CT - 1) / CT, CT>>>((const float4*)(src), \
            (__nv_bfloat162*)(dh), (__nv_bfloat162*)(dl), (n) / 4)

    // --- split inputs needed by GEMM1 ---
    CVT(x,     xhi, xlo, MROWS * DMODEL);
    CVT(W_in,  Wih, Wil, 2 * DINNER * DMODEL);
    // --- weight splits (independent) ---
    cvt_hl_pad_wx<<<(XPITCH * DINNER / 4 + CT - 1) / CT, CT>>>(
        W_x, (__nv_bfloat162*)Wxh, (__nv_bfloat162*)Wxl);
    CVT(W_dt,  Wdh, Wdl, DINNER * DTRANK);
    CVT(W_out, Woh, Wol, DMODEL * DINNER);

    // 1) xz = x @ W_in^T   [2048, 4096], K=1024
    {
        dim3 grid((2 * DINNER) / BNT, MROWS / BMT);
        gemm_mma<0><<<grid, 256, GSMEM>>>(xhi, xlo, DMODEL, Wih, Wil, DMODEL,
                                          nullptr, p_xz, 2 * DINNER, DMODEL);
    }
    // 2) causal conv + silu; silu(z)
    conv_silu_kernel<<<(MROWS * DINNER + CT - 1) / CT, CT>>>(W_conv, b_conv);
    CVT(p_xconv, xch, xcl, MROWS * DINNER);

    // 3) x_dbl = x_conv @ W_x^T   [2048, 128(pad)], K=2048
    {
        dim3 grid(XPITCH / BNT, MROWS / BMT);
        gemm_mma<0><<<grid, 256, GSMEM>>>(xch, xcl, DINNER, Wxh, Wxl, DINNER,
                                          nullptr, p_xdbl, XPITCH, DINNER);
    }
    CVT(p_xdbl, xdh, xdl, MROWS * XPITCH);

    // 4) dt = softplus(x_dbl[:, :64] @ W_dt^T + b_dt)   [2048, 2048], K=64
    {
        dim3 grid(DINNER / BNT, MROWS / BMT);
        gemm_mma<1><<<grid, 256, GSMEM>>>(xdh, xdl, XPITCH, Wdh, Wdl, DTRANK,
                                          b_dt, p_dt, DINNER, DTRANK);
    }
    // 5) selective scan (+ skip + gate fused)
    scan_kernel<<<BATCH * DINNER * DSTATE / CT, CT>>>(A_log, Dp);
    CVT(p_y, yh, yl, MROWS * DINNER);

    // 6) out = gated @ W_out^T   [2048, 1024], K=2048
    {
        dim3 grid(DMODEL / BNT, MROWS / BMT);
        gemm_mma<0><<<grid, 256, GSMEM>>>(yh, yl, DINNER, Woh, Wol, DINNER,
                                          nullptr, out, DMODEL, DINNER);
    }
    (void)in_sizes; (void)n_in; (void)out_size;
}

// round 9
// speedup vs baseline: 3.7151x; 1.5805x over previous
#include <cuda_runtime.h>
#include <cuda_bf16.h>
#include <math.h>
#include <stdint.h>

// ---------------------------------------------------------------------------
// SelectiveSSM (Mamba block) — pre-split bf16 hi/lo operands + cp.async
// double-buffered mma.sync GEMMs + smem-staged selective scan.
// B=2, L=1024, D_MODEL=1024, D_INNER=2048, D_STATE=16, DT_RANK=64, D_CONV=4
// ---------------------------------------------------------------------------

#define BATCH   2
#define SEQ     1024
#define DMODEL  1024
#define DINNER  2048
#define DSTATE  16
#define DTRANK  64
#define DCONV   4
#define MROWS   (BATCH * SEQ)          // 2048
#define XPITCH  128                    // padded x_dbl width (logical 96)

// -------------------- fp32 scratch -----------------------------------------
__device__ float g_xz[MROWS * 2 * DINNER];     // [2048, 4096]
__device__ float g_xconv[MROWS * DINNER];      // [2048, 2048]
__device__ float g_zsilu[MROWS * DINNER];      // [2048, 2048]
__device__ float g_xdbl[MROWS * XPITCH];       // [2048, 128] (cols 96.. = 0)
__device__ float g_dt[MROWS * DINNER];         // [2048, 2048]

// -------------------- bf16 hi/lo planes ------------------------------------
__device__ __nv_bfloat16 g_xhi[MROWS * DMODEL],   g_xlo[MROWS * DMODEL];
__device__ __nv_bfloat16 g_Wih[2 * DINNER * DMODEL], g_Wil[2 * DINNER * DMODEL];
__device__ __nv_bfloat16 g_xch[MROWS * DINNER],   g_xcl[MROWS * DINNER];
__device__ __nv_bfloat16 g_Wxh[XPITCH * DINNER],  g_Wxl[XPITCH * DINNER];
__device__ __nv_bfloat16 g_xdh[MROWS * XPITCH],   g_xdl[MROWS * XPITCH];
__device__ __nv_bfloat16 g_Wdh[DINNER * DTRANK],  g_Wdl[DINNER * DTRANK];
__device__ __nv_bfloat16 g_yh[MROWS * DINNER],    g_yl[MROWS * DINNER];
__device__ __nv_bfloat16 g_Woh[DMODEL * DINNER],  g_Wol[DMODEL * DINNER];

// ===================== PTX helpers (sm_80+ only) ===========================
__device__ __forceinline__ uint32_t smem_u32(const void* p) {
    uint32_t a;
    asm("{ .reg .u64 t; cvta.to.shared.u64 t, %1; cvt.u32.u64 %0, t; }"
        : "=r"(a) : "l"(p));
    return a;
}
__device__ __forceinline__ void ldsm_x4(uint32_t* r, uint32_t addr) {
    asm volatile("ldmatrix.sync.aligned.m8n8.x4.shared.b16 {%0,%1,%2,%3}, [%4];"
        : "=r"(r[0]), "=r"(r[1]), "=r"(r[2]), "=r"(r[3]) : "r"(addr));
}
__device__ __forceinline__ void ldsm_x2(uint32_t* r, uint32_t addr) {
    asm volatile("ldmatrix.sync.aligned.m8n8.x2.shared.b16 {%0,%1}, [%2];"
        : "=r"(r[0]), "=r"(r[1]) : "r"(addr));
}
__device__ __forceinline__ void mma16816(float* c, const uint32_t* a,
                                         const uint32_t* b) {
    asm volatile("mma.sync.aligned.m16n8k16.row.col.f32.bf16.bf16.f32 "
        "{%0,%1,%2,%3}, {%4,%5,%6,%7}, {%8,%9}, {%0,%1,%2,%3};"
        : "+f"(c[0]), "+f"(c[1]), "+f"(c[2]), "+f"(c[3])
        : "r"(a[0]), "r"(a[1]), "r"(a[2]), "r"(a[3]), "r"(b[0]), "r"(b[1]));
}
#define CPA16(dst, src) \
    asm volatile("cp.async.cg.shared.global [%0], [%1], 16;" \
                 :: "r"(dst), "l"(src) : "memory")
#define CPA4(dst, src) \
    asm volatile("cp.async.ca.shared.global [%0], [%1], 4;" \
                 :: "r"(dst), "l"(src) : "memory")
#define CP_COMMIT() asm volatile("cp.async.commit_group;" ::: "memory")

// ---------------------------------------------------------------------------
// Tensor-core GEMM on pre-split operands (3-term Markidis split).
// CTA tile 128x64, BK=32, 256 threads (8 warps: 4m x 2n, warptile 32x32).
// ---------------------------------------------------------------------------
#define BMT   128
#define BNT   64
#define BKT   32
#define PITCH 40
#define A_PLANE 10240u   // 128*40*2 bytes
#define B_PLANE 5120u    // 64*40*2 bytes
#define GSMEM   61440    // 2 bufs * 2 planes * (A_PLANE + B_PLANE)

__device__ __forceinline__ void cpa_fill(
    uint32_t sAh, uint32_t sAl, uint32_t sBh, uint32_t sBl,
    const __nv_bfloat16* Ahi, const __nv_bfloat16* Alo, int lda,
    const __nv_bfloat16* Whi, const __nv_bfloat16* Wlo, int ldw,
    int row0, int col0, int k0, int tid)
{
#pragma unroll
    for (int it = 0; it < 2; it++) {
        int idx = it * 256 + tid;
        int r = idx >> 2, ch = idx & 3;
        const size_t aoff = (size_t)(row0 + r) * lda + k0 + ch * 8;
        const uint32_t sd = (uint32_t)(r * 80 + ch * 16);
        CPA16(sAh + sd, Ahi + aoff);
        CPA16(sAl + sd, Alo + aoff);
    }
    {
        int r = tid >> 2, ch = tid & 3;
        const size_t boff = (size_t)(col0 + r) * ldw + k0 + ch * 8;
        const uint32_t sd = (uint32_t)(r * 80 + ch * 16);
        CPA16(sBh + sd, Whi + boff);
        CPA16(sBl + sd, Wlo + boff);
    }
    CP_COMMIT();
}

template<int EPI>
__global__ __launch_bounds__(256, 2)
void gemm_mma(const __nv_bfloat16* __restrict__ Ahi,
              const __nv_bfloat16* __restrict__ Alo, int lda,
              const __nv_bfloat16* __restrict__ Whi,
              const __nv_bfloat16* __restrict__ Wlo, int ldw,
              const float* __restrict__ bias,
              float* __restrict__ C, int ldc, int K)
{
    extern __shared__ char smem[];
    const uint32_t sb = smem_u32(smem);
    const uint32_t aB[2][2] = {{sb, sb + A_PLANE},
                               {sb + 2 * A_PLANE, sb + 3 * A_PLANE}};
    const uint32_t bB[2][2] = {{sb + 4 * A_PLANE, sb + 4 * A_PLANE + B_PLANE},
                               {sb + 4 * A_PLANE + 2 * B_PLANE,
                                sb + 4 * A_PLANE + 3 * B_PLANE}};

    const int tid  = threadIdx.x;
    const int lane = tid & 31;
    const int wid  = tid >> 5;
    const int wm   = wid >> 1;
    const int wn   = wid & 1;
    const int row0 = blockIdx.y * BMT;
    const int col0 = blockIdx.x * BNT;

    const int a_r = lane & 15, a_k = (lane >> 4) << 3;
    const int b_r = lane & 7,  b_k = ((lane >> 3) & 1) << 3;

    float acc[2][4][4];
#pragma unroll
    for (int mi = 0; mi < 2; mi++)
#pragma unroll
        for (int ni = 0; ni < 4; ni++)
#pragma unroll
            for (int j = 0; j < 4; j++) acc[mi][ni][j] = 0.f;

    const int nit = K / BKT;
    cpa_fill(aB[0][0], aB[0][1], bB[0][0], bB[0][1],
             Ahi, Alo, lda, Whi, Wlo, ldw, row0, col0, 0, tid);

    for (int c = 0; c < nit; c++) {
        const int cur = c & 1;
        if (c + 1 < nit) {
            cpa_fill(aB[cur ^ 1][0], aB[cur ^ 1][1], bB[cur ^ 1][0], bB[cur ^ 1][1],
                     Ahi, Alo, lda, Whi, Wlo, ldw, row0, col0, (c + 1) * BKT, tid);
            asm volatile("cp.async.wait_group 1;" ::: "memory");
        } else {
            asm volatile("cp.async.wait_group 0;" ::: "memory");
        }
        __syncthreads();

#pragma unroll
        for (int s = 0; s < 2; s++) {
            uint32_t ah[2][4], al[2][4], bh[4][2], bl[4][2];
#pragma unroll
            for (int mi = 0; mi < 2; mi++) {
                uint32_t e = (uint32_t)((wm * 32 + mi * 16 + a_r) * PITCH
                                        + s * 16 + a_k) * 2u;
                ldsm_x4(ah[mi], aB[cur][0] + e);
                ldsm_x4(al[mi], aB[cur][1] + e);
            }
#pragma unroll
            for (int ni = 0; ni < 4; ni++) {
                uint32_t e = (uint32_t)((wn * 32 + ni * 8 + b_r) * PITCH
                                        + s * 16 + b_k) * 2u;
                ldsm_x2(bh[ni], bB[cur][0] + e);
                ldsm_x2(bl[ni], bB[cur][1] + e);
            }
#pragma unroll
            for (int mi = 0; mi < 2; mi++)
#pragma unroll
                for (int ni = 0; ni < 4; ni++) {
                    mma16816(acc[mi][ni], ah[mi], bh[ni]);
                    mma16816(acc[mi][ni], ah[mi], bl[ni]);
                    mma16816(acc[mi][ni], al[mi], bh[ni]);
                }
        }
        __syncthreads();
    }

    const int cr = lane >> 2;
    const int cc = (lane & 3) * 2;
#pragma unroll
    for (int mi = 0; mi < 2; mi++) {
#pragma unroll
        for (int ni = 0; ni < 4; ni++) {
            int row = row0 + wm * 32 + mi * 16 + cr;
            int col = col0 + wn * 32 + ni * 8 + cc;
            float v[4] = {acc[mi][ni][0], acc[mi][ni][1],
                          acc[mi][ni][2], acc[mi][ni][3]};
            if (EPI == 1) {
#pragma unroll
                for (int j = 0; j < 4; j++) {
                    float t = v[j] + bias[col + (j & 1)];
                    v[j] = (t > 20.f) ? t : log1pf(__expf(t));
                }
            }
            *(float2*)(C + (size_t)row * ldc + col)       = make_float2(v[0], v[1]);
            *(float2*)(C + (size_t)(row + 8) * ldc + col) = make_float2(v[2], v[3]);
        }
    }
}

// -------------------- fp32 -> bf16 hi/lo converters ------------------------
__global__ void cvt_hl(const float4* __restrict__ in,
                       __nv_bfloat162* __restrict__ hi,
                       __nv_bfloat162* __restrict__ lo, int n4)
{
    int i = blockIdx.x * blockDim.x + threadIdx.x;
    if (i >= n4) return;
    float4 v = in[i];
    float f[4] = {v.x, v.y, v.z, v.w};
    __nv_bfloat16 h[4], l[4];
#pragma unroll
    for (int j = 0; j < 4; j++) {
        h[j] = __float2bfloat16(f[j]);
        l[j] = __float2bfloat16(f[j] - __bfloat162float(h[j]));
    }
    hi[2 * i]     = __nv_bfloat162(h[0], h[1]);
    hi[2 * i + 1] = __nv_bfloat162(h[2], h[3]);
    lo[2 * i]     = __nv_bfloat162(l[0], l[1]);
    lo[2 * i + 1] = __nv_bfloat162(l[2], l[3]);
}

// W_x [96, 2048] -> padded [128, 2048] hi/lo (rows 96..127 zero)
__global__ void cvt_hl_pad_wx(const float* __restrict__ in,
                              __nv_bfloat162* __restrict__ hi,
                              __nv_bfloat162* __restrict__ lo)
{
    int i = blockIdx.x * blockDim.x + threadIdx.x;
    if (i >= XPITCH * DINNER / 4) return;
    int row = i >> 9;
    int col4 = (i & 511) << 2;
    float f[4] = {0.f, 0.f, 0.f, 0.f};
    if (row < 96) {
        float4 v = *(const float4*)(in + (size_t)row * DINNER + col4);
        f[0] = v.x; f[1] = v.y; f[2] = v.z; f[3] = v.w;
    }
    __nv_bfloat16 h[4], l[4];
#pragma unroll
    for (int j = 0; j < 4; j++) {
        h[j] = __float2bfloat16(f[j]);
        l[j] = __float2bfloat16(f[j] - __bfloat162float(h[j]));
    }
    hi[2 * i]     = __nv_bfloat162(h[0], h[1]);
    hi[2 * i + 1] = __nv_bfloat162(h[2], h[3]);
    lo[2 * i]     = __nv_bfloat162(l[0], l[1]);
    lo[2 * i + 1] = __nv_bfloat162(l[2], l[3]);
}

// -------------------- causal conv1d + SiLU + z gate (+ inline split) -------
__global__ void conv_silu_kernel(const float* __restrict__ Wc,   // [DINNER,4]
                                 const float* __restrict__ bc)   // [DINNER]
{
    int i = blockIdx.x * blockDim.x + threadIdx.x;      // over MROWS*DINNER
    if (i >= MROWS * DINNER) return;
    int d = i & (DINNER - 1);
    int m = i >> 11;                                    // b*SEQ + l
    int b = m >> 10;
    int l = m & (SEQ - 1);

    float acc = bc[d];
#pragma unroll
    for (int k = 0; k < DCONV; k++) {
        int lt = l - (DCONV - 1) + k;
        if (lt >= 0)
            acc = fmaf(Wc[d * DCONV + k],
                       g_xz[(size_t)((b << 10) + lt) * (2 * DINNER) + d], acc);
    }
    float xc = acc / (1.f + __expf(-acc));              // silu
    g_xconv[i] = xc;
    __nv_bfloat16 hb = __float2bfloat16(xc);
    g_xch[i] = hb;
    g_xcl[i] = __float2bfloat16(xc - __bfloat162float(hb));

    float zv = g_xz[(size_t)m * (2 * DINNER) + DINNER + d];
    g_zsilu[i] = zv / (1.f + __expf(-zv));
}

// ---------------------------------------------------------------------------
// Selective scan v2 — smem-staged, cp.async double-buffered.
// 256 CTAs x 256 threads. CTA owns 16 channels x 16 states.
// Stage = 64 timesteps. Emits gated output directly as bf16 hi/lo planes.
// ---------------------------------------------------------------------------
#define SCH 16
#define STT 64
#define NSTAGE (SEQ / STT)   // 16
#define BCP 36               // padded B/C row (floats); 144 B = 9*16 (aligned)

__global__ __launch_bounds__(256)
void scan_kernel(const float* __restrict__ A_log,   // [DINNER,16]
                 const float* __restrict__ Dp)      // [DINNER]
{
    __shared__ alignas(16) float s_dt[2][SCH][STT];
    __shared__ alignas(16) float s_xc[2][SCH][STT];
    __shared__ alignas(16) float s_zs[2][SCH][STT];
    __shared__ alignas(16) float s_bc[2][STT][BCP];

    const int tid = threadIdx.x;
    const int c = tid >> 4;              // channel within CTA (0..15)
    const int n = tid & 15;              // state
    const int chg = blockIdx.x * SCH;    // global channel base (0..4095)
    const int b  = chg >> 11;
    const int d0 = chg & (DINNER - 1);
    const size_t mb = (size_t)b * SEQ;

    const float A  = -__expf(A_log[(d0 + c) * DSTATE + n]);
    const float Dv = Dp[d0 + c];

    const uint32_t u_dt = smem_u32(s_dt), u_xc = smem_u32(s_xc);
    const uint32_t u_zs = smem_u32(s_zs), u_bc = smem_u32(s_bc);

    // fill stage s with timesteps [t0, t0+64)
    auto fill = [&](int s, int t0) {
#pragma unroll
        for (int i = 0; i < 4; i++) {
            int idx = i * 256 + tid;
            int ch = idx >> 6, t = idx & 63;
            size_t g = (mb + t0 + t) * DINNER + d0 + ch;
            uint32_t so = (uint32_t)(((s * SCH + ch) * STT + t) * 4);
            CPA4(u_dt + so, g_dt + g);
            CPA4(u_xc + so, g_xconv + g);
            CPA4(u_zs + so, g_zsilu + g);
        }
#pragma unroll
        for (int i = 0; i < 2; i++) {
            int idx = i * 256 + tid;
            int t = idx >> 3, chk = idx & 7;
            const float* src = g_xdbl + (mb + t0 + t) * XPITCH + DTRANK + chk * 4;
            uint32_t dst = u_bc + (uint32_t)(((s * STT + t) * BCP + chk * 4) * 4);
            CPA16(dst, src);
        }
        CP_COMMIT();
    };

    fill(0, 0);
    float h = 0.f;

    for (int st = 0; st < NSTAGE; st++) {
        const int cur = st & 1;
        if (st + 1 < NSTAGE) {
            fill(cur ^ 1, (st + 1) * STT);
            asm volatile("cp.async.wait_group 1;" ::: "memory");
        } else {
            asm volatile("cp.async.wait_group 0;" ::: "memory");
        }
        __syncthreads();

        const int t0 = st * STT;
#pragma unroll 4
        for (int t = 0; t < STT; t++) {
            float dtv = s_dt[cur][c][t];
            float xv  = s_xc[cur][c][t];
            float Bv  = s_bc[cur][t][n];
            float Cv  = s_bc[cur][t][16 + n];
            h = __expf(dtv * A) * h + dtv * Bv * xv;
            float yv = h * Cv;
            yv += __shfl_xor_sync(0xffffffffu, yv, 1);
            yv += __shfl_xor_sync(0xffffffffu, yv, 2);
            yv += __shfl_xor_sync(0xffffffffu, yv, 4);
            yv += __shfl_xor_sync(0xffffffffu, yv, 8);
            if (n == 0) {
                float yo = (yv + xv * Dv) * s_zs[cur][c][t];
                __nv_bfloat16 hb = __float2bfloat16(yo);
                __nv_bfloat16 lb = __float2bfloat16(yo - __bfloat162float(hb));
                size_t o = (mb + t0 + t) * DINNER + d0 + c;
                g_yh[o] = hb;
                g_yl[o] = lb;
            }
        }
        __syncthreads();
    }
}

// -------------------- host launcher ----------------------------------------
extern "C" void kernel_launch(void* const* d_in, const int* in_sizes, int n_in,
                              void* d_out, int out_size)
{
    const float* x      = (const float*)d_in[0];
    const float* W_in   = (const float*)d_in[1];
    const float* W_conv = (const float*)d_in[2];
    const float* b_conv = (const float*)d_in[3];
    const float* W_x    = (const float*)d_in[4];
    const float* W_dt   = (const float*)d_in[5];
    const float* b_dt   = (const float*)d_in[6];
    const float* A_log  = (const float*)d_in[7];
    const float* Dp     = (const float*)d_in[8];
    const float* W_out  = (const float*)d_in[9];
    float* out = (float*)d_out;

    float *p_xz, *p_xdbl, *p_dt;
    cudaGetSymbolAddress((void**)&p_xz,   g_xz);
    cudaGetSymbolAddress((void**)&p_xdbl, g_xdbl);
    cudaGetSymbolAddress((void**)&p_dt,   g_dt);

    __nv_bfloat16 *xhi, *xlo, *Wih, *Wil, *xch, *xcl, *Wxh, *Wxl;
    __nv_bfloat16 *xdh, *xdl, *Wdh, *Wdl, *yh, *yl, *Woh, *Wol;
    cudaGetSymbolAddress((void**)&xhi, g_xhi); cudaGetSymbolAddress((void**)&xlo, g_xlo);
    cudaGetSymbolAddress((void**)&Wih, g_Wih); cudaGetSymbolAddress((void**)&Wil, g_Wil);
    cudaGetSymbolAddress((void**)&xch, g_xch); cudaGetSymbolAddress((void**)&xcl, g_xcl);
    cudaGetSymbolAddress((void**)&Wxh, g_Wxh); cudaGetSymbolAddress((void**)&Wxl, g_Wxl);
    cudaGetSymbolAddress((void**)&xdh, g_xdh); cudaGetSymbolAddress((void**)&xdl, g_xdl);
    cudaGetSymbolAddress((void**)&Wdh, g_Wdh); cudaGetSymbolAddress((void**)&Wdl, g_Wdl);
    cudaGetSymbolAddress((void**)&yh,  g_yh);  cudaGetSymbolAddress((void**)&yl,  g_yl);
    cudaGetSymbolAddress((void**)&Woh, g_Woh); cudaGetSymbolAddress((void**)&Wol, g_Wol);

    cudaFuncSetAttribute(gemm_mma<0>, cudaFuncAttributeMaxDynamicSharedMemorySize, GSMEM);
    cudaFuncSetAttribute(gemm_mma<1>, cudaFuncAttributeMaxDynamicSharedMemorySize, GSMEM);

    const int CT = 256;
    #define CVT(src, dh, dl, n) \
        cvt_hl<<<((n) / 4 + CT - 1) / CT, CT>>>((const float4*)(src), \
            (__nv_bfloat162*)(dh), (__nv_bfloat162*)(dl), (n) / 4)

    // launch 0,1,2: splits needed by GEMM1 (+pad) — GEMM1 lands at index 3
    CVT(x,     xhi, xlo, MROWS * DMODEL);
    CVT(W_in,  Wih, Wil, 2 * DINNER * DMODEL);
    cvt_hl_pad_wx<<<(XPITCH * DINNER / 4 + CT - 1) / CT, CT>>>(
        W_x, (__nv_bfloat162*)Wxh, (__nv_bfloat162*)Wxl);

    // 3) xz = x @ W_in^T   [2048, 4096], K=1024
    {
        dim3 grid((2 * DINNER) / BNT, MROWS / BMT);
        gemm_mma<0><<<grid, 256, GSMEM>>>(xhi, xlo, DMODEL, Wih, Wil, DMODEL,
                                          nullptr, p_xz, 2 * DINNER, DMODEL);
    }
    // remaining weight splits (independent of GEMM1)
    CVT(W_dt,  Wdh, Wdl, DINNER * DTRANK);
    CVT(W_out, Woh, Wol, DMODEL * DINNER);

    // causal conv + silu + z gate (+ xconv hi/lo split fused)
    conv_silu_kernel<<<(MROWS * DINNER + CT - 1) / CT, CT>>>(W_conv, b_conv);

    // x_dbl = x_conv @ W_x^T   [2048, 128(pad)], K=2048
    {
        dim3 grid(XPITCH / BNT, MROWS / BMT);
        gemm_mma<0><<<grid, 256, GSMEM>>>(xch, xcl, DINNER, Wxh, Wxl, DINNER,
                                          nullptr, p_xdbl, XPITCH, DINNER);
    }
    CVT(p_xdbl, xdh, xdl, MROWS * XPITCH);

    // dt = softplus(x_dbl[:, :64] @ W_dt^T + b_dt)   [2048, 2048], K=64
    {
        dim3 grid(DINNER / BNT, MROWS / BMT);
        gemm_mma<1><<<grid, 256, GSMEM>>>(xdh, xdl, XPITCH, Wdh, Wdl, DTRANK,
                                          b_dt, p_dt, DINNER, DTRANK);
    }
    // selective scan (+ skip + gate fused, emits bf16 hi/lo directly)
    scan_kernel<<<BATCH * DINNER / SCH, 256>>>(A_log, Dp);

    // out = gated @ W_out^T   [2048, 1024], K=2048
    {
        dim3 grid(DMODEL / BNT, MROWS / BMT);
        gemm_mma<0><<<grid, 256, GSMEM>>>(yh, yl, DINNER, Woh, Wol, DINNER,
                                          nullptr, out, DMODEL, DINNER);
    }
    (void)in_sizes; (void)n_in; (void)out_size;
}

// round 11
// speedup vs baseline: 3.7835x; 1.0184x over previous
#include <cuda_runtime.h>
#include <cuda_bf16.h>
#include <math.h>
#include <stdint.h>

// ---------------------------------------------------------------------------
// SelectiveSSM (Mamba block) — pre-split bf16 hi/lo operands + cp.async
// double-buffered mma.sync GEMMs (128x128 tile) + smem-staged selective scan.
// B=2, L=1024, D_MODEL=1024, D_INNER=2048, D_STATE=16, DT_RANK=64, D_CONV=4
// ---------------------------------------------------------------------------

#define BATCH   2
#define SEQ     1024
#define DMODEL  1024
#define DINNER  2048
#define DSTATE  16
#define DTRANK  64
#define DCONV   4
#define MROWS   (BATCH * SEQ)          // 2048
#define XPITCH  128                    // padded x_dbl width (logical 96)

// -------------------- fp32 scratch -----------------------------------------
__device__ float g_xz[MROWS * 2 * DINNER];     // [2048, 4096]
__device__ float g_xconv[MROWS * DINNER];      // [2048, 2048]
__device__ float g_zsilu[MROWS * DINNER];      // [2048, 2048]
__device__ float g_xdbl[MROWS * XPITCH];       // [2048, 128] (cols 96.. = 0)
__device__ float g_dt[MROWS * DINNER];         // [2048, 2048]

// -------------------- bf16 hi/lo planes ------------------------------------
__device__ __nv_bfloat16 g_xhi[MROWS * DMODEL],   g_xlo[MROWS * DMODEL];
__device__ __nv_bfloat16 g_Wih[2 * DINNER * DMODEL], g_Wil[2 * DINNER * DMODEL];
__device__ __nv_bfloat16 g_xch[MROWS * DINNER],   g_xcl[MROWS * DINNER];
__device__ __nv_bfloat16 g_Wxh[XPITCH * DINNER],  g_Wxl[XPITCH * DINNER];
__device__ __nv_bfloat16 g_xdh[MROWS * XPITCH],   g_xdl[MROWS * XPITCH];
__device__ __nv_bfloat16 g_Wdh[DINNER * DTRANK],  g_Wdl[DINNER * DTRANK];
__device__ __nv_bfloat16 g_yh[MROWS * DINNER],    g_yl[MROWS * DINNER];
__device__ __nv_bfloat16 g_Woh[DMODEL * DINNER],  g_Wol[DMODEL * DINNER];

// ===================== PTX helpers (sm_80+ only) ===========================
__device__ __forceinline__ uint32_t smem_u32(const void* p) {
    uint32_t a;
    asm("{ .reg .u64 t; cvta.to.shared.u64 t, %1; cvt.u32.u64 %0, t; }"
        : "=r"(a) : "l"(p));
    return a;
}
__device__ __forceinline__ void ldsm_x4(uint32_t* r, uint32_t addr) {
    asm volatile("ldmatrix.sync.aligned.m8n8.x4.shared.b16 {%0,%1,%2,%3}, [%4];"
        : "=r"(r[0]), "=r"(r[1]), "=r"(r[2]), "=r"(r[3]) : "r"(addr));
}
__device__ __forceinline__ void ldsm_x2(uint32_t* r, uint32_t addr) {
    asm volatile("ldmatrix.sync.aligned.m8n8.x2.shared.b16 {%0,%1}, [%2];"
        : "=r"(r[0]), "=r"(r[1]) : "r"(addr));
}
__device__ __forceinline__ void mma16816(float* c, const uint32_t* a,
                                         const uint32_t* b) {
    asm volatile("mma.sync.aligned.m16n8k16.row.col.f32.bf16.bf16.f32 "
        "{%0,%1,%2,%3}, {%4,%5,%6,%7}, {%8,%9}, {%0,%1,%2,%3};"
        : "+f"(c[0]), "+f"(c[1]), "+f"(c[2]), "+f"(c[3])
        : "r"(a[0]), "r"(a[1]), "r"(a[2]), "r"(a[3]), "r"(b[0]), "r"(b[1]));
}
#define CPA16(dst, src) \
    asm volatile("cp.async.cg.shared.global [%0], [%1], 16;" \
                 :: "r"(dst), "l"(src) : "memory")
#define CPA4(dst, src) \
    asm volatile("cp.async.ca.shared.global [%0], [%1], 4;" \
                 :: "r"(dst), "l"(src) : "memory")
#define CP_COMMIT() asm volatile("cp.async.commit_group;" ::: "memory")

// ---------------------------------------------------------------------------
// Tensor-core GEMM on pre-split operands (3-term Markidis split).
// CTA tile 128x128, BK=32, 256 threads (8 warps: 4m x 2n, warptile 32x64).
// blockIdx.z = split-K chunk (K param = chunk length, kbase = z*K).
// EPI: 0 = plain store, 1 = softplus(acc+bias) store, 2 = atomicAdd.
// ---------------------------------------------------------------------------
#define BMT   128
#define BNT   128
#define BKT   32
#define PITCH 40
#define A_PLANE 10240u   // 128*40*2 bytes
#define B_PLANE 10240u   // 128*40*2 bytes
#define GSMEM   81920    // 2 bufs * 2 planes * (A_PLANE + B_PLANE)

__device__ __forceinline__ void cpa_fill(
    uint32_t sAh, uint32_t sAl, uint32_t sBh, uint32_t sBl,
    const __nv_bfloat16* Ahi, const __nv_bfloat16* Alo, int lda,
    const __nv_bfloat16* Whi, const __nv_bfloat16* Wlo, int ldw,
    int row0, int col0, int k0, int tid)
{
#pragma unroll
    for (int it = 0; it < 2; it++) {
        int idx = it * 256 + tid;
        int r = idx >> 2, ch = idx & 3;
        const size_t aoff = (size_t)(row0 + r) * lda + k0 + ch * 8;
        const size_t boff = (size_t)(col0 + r) * ldw + k0 + ch * 8;
        const uint32_t sd = (uint32_t)(r * 80 + ch * 16);
        CPA16(sAh + sd, Ahi + aoff);
        CPA16(sAl + sd, Alo + aoff);
        CPA16(sBh + sd, Whi + boff);
        CPA16(sBl + sd, Wlo + boff);
    }
    CP_COMMIT();
}

template<int EPI>
__global__ __launch_bounds__(256, 1)
void gemm_mma(const __nv_bfloat16* __restrict__ Ahi,
              const __nv_bfloat16* __restrict__ Alo, int lda,
              const __nv_bfloat16* __restrict__ Whi,
              const __nv_bfloat16* __restrict__ Wlo, int ldw,
              const float* __restrict__ bias,
              float* __restrict__ C, int ldc, int K)
{
    extern __shared__ char smem[];
    const uint32_t sb = smem_u32(smem);
    const uint32_t aB[2][2] = {{sb, sb + A_PLANE},
                               {sb + 2 * A_PLANE, sb + 3 * A_PLANE}};
    const uint32_t bB[2][2] = {{sb + 4 * A_PLANE, sb + 4 * A_PLANE + B_PLANE},
                               {sb + 4 * A_PLANE + 2 * B_PLANE,
                                sb + 4 * A_PLANE + 3 * B_PLANE}};

    const int tid  = threadIdx.x;
    const int lane = tid & 31;
    const int wid  = tid >> 5;
    const int wm   = wid >> 1;           // 0..3 (32 rows each)
    const int wn   = wid & 1;            // 0..1 (64 cols each)
    const int row0 = blockIdx.y * BMT;
    const int col0 = blockIdx.x * BNT;
    const int kbase = blockIdx.z * K;    // split-K chunk base

    const int a_r = lane & 15, a_k = (lane >> 4) << 3;
    const int b_r = lane & 7,  b_k = ((lane >> 3) & 1) << 3;

    float acc[2][8][4];
#pragma unroll
    for (int mi = 0; mi < 2; mi++)
#pragma unroll
        for (int ni = 0; ni < 8; ni++)
#pragma unroll
            for (int j = 0; j < 4; j++) acc[mi][ni][j] = 0.f;

    const int nit = K / BKT;
    cpa_fill(aB[0][0], aB[0][1], bB[0][0], bB[0][1],
             Ahi, Alo, lda, Whi, Wlo, ldw, row0, col0, kbase, tid);

    for (int c = 0; c < nit; c++) {
        const int cur = c & 1;
        if (c + 1 < nit) {
            cpa_fill(aB[cur ^ 1][0], aB[cur ^ 1][1], bB[cur ^ 1][0], bB[cur ^ 1][1],
                     Ahi, Alo, lda, Whi, Wlo, ldw, row0, col0,
                     kbase + (c + 1) * BKT, tid);
            asm volatile("cp.async.wait_group 1;" ::: "memory");
        } else {
            asm volatile("cp.async.wait_group 0;" ::: "memory");
        }
        __syncthreads();

#pragma unroll
        for (int s = 0; s < 2; s++) {
            uint32_t ah[2][4], al[2][4], bh[8][2], bl[8][2];
#pragma unroll
            for (int mi = 0; mi < 2; mi++) {
                uint32_t e = (uint32_t)((wm * 32 + mi * 16 + a_r) * PITCH
                                        + s * 16 + a_k) * 2u;
                ldsm_x4(ah[mi], aB[cur][0] + e);
                ldsm_x4(al[mi], aB[cur][1] + e);
            }
#pragma unroll
            for (int ni = 0; ni < 8; ni++) {
                uint32_t e = (uint32_t)((wn * 64 + ni * 8 + b_r) * PITCH
                                        + s * 16 + b_k) * 2u;
                ldsm_x2(bh[ni], bB[cur][0] + e);
                ldsm_x2(bl[ni], bB[cur][1] + e);
            }
#pragma unroll
            for (int mi = 0; mi < 2; mi++)
#pragma unroll
                for (int ni = 0; ni < 8; ni++) {
                    mma16816(acc[mi][ni], ah[mi], bh[ni]);
                    mma16816(acc[mi][ni], ah[mi], bl[ni]);
                    mma16816(acc[mi][ni], al[mi], bh[ni]);
                }
        }
        __syncthreads();
    }

    // ---- epilogue ----
    const int cr = lane >> 2;
    const int cc = (lane & 3) * 2;
#pragma unroll
    for (int mi = 0; mi < 2; mi++) {
#pragma unroll
        for (int ni = 0; ni < 8; ni++) {
            int row = row0 + wm * 32 + mi * 16 + cr;
            int col = col0 + wn * 64 + ni * 8 + cc;
            float v[4] = {acc[mi][ni][0], acc[mi][ni][1],
                          acc[mi][ni][2], acc[mi][ni][3]};
            if (EPI == 1) {
#pragma unroll
                for (int j = 0; j < 4; j++) {
                    float t = v[j] + bias[col + (j & 1)];
                    v[j] = (t > 20.f) ? t : log1pf(__expf(t));
                }
            }
            if (EPI == 2) {
                atomicAdd(C + (size_t)row * ldc + col,           v[0]);
                atomicAdd(C + (size_t)row * ldc + col + 1,       v[1]);
                atomicAdd(C + (size_t)(row + 8) * ldc + col,     v[2]);
                atomicAdd(C + (size_t)(row + 8) * ldc + col + 1, v[3]);
            } else {
                *(float2*)(C + (size_t)row * ldc + col)       = make_float2(v[0], v[1]);
                *(float2*)(C + (size_t)(row + 8) * ldc + col) = make_float2(v[2], v[3]);
            }
        }
    }
}

// -------------------- zero-fill (graph-safe memset replacement) ------------
__global__ void zero_xdbl()
{
    int i = blockIdx.x * blockDim.x + threadIdx.x;   // over MROWS*XPITCH/4
    if (i < MROWS * XPITCH / 4)
        reinterpret_cast<float4*>(g_xdbl)[i] = make_float4(0.f, 0.f, 0.f, 0.f);
}

// -------------------- fp32 -> bf16 hi/lo converters ------------------------
__global__ void cvt_hl(const float4* __restrict__ in,
                       __nv_bfloat162* __restrict__ hi,
                       __nv_bfloat162* __restrict__ lo, int n4)
{
    int i = blockIdx.x * blockDim.x + threadIdx.x;
    if (i >= n4) return;
    float4 v = in[i];
    float f[4] = {v.x, v.y, v.z, v.w};
    __nv_bfloat16 h[4], l[4];
#pragma unroll
    for (int j = 0; j < 4; j++) {
        h[j] = __float2bfloat16(f[j]);
        l[j] = __float2bfloat16(f[j] - __bfloat162float(h[j]));
    }
    hi[2 * i]     = __nv_bfloat162(h[0], h[1]);
    hi[2 * i + 1] = __nv_bfloat162(h[2], h[3]);
    lo[2 * i]     = __nv_bfloat162(l[0], l[1]);
    lo[2 * i + 1] = __nv_bfloat162(l[2], l[3]);
}

// W_x [96, 2048] -> padded [128, 2048] hi/lo (rows 96..127 zero)
__global__ void cvt_hl_pad_wx(const float* __restrict__ in,
                              __nv_bfloat162* __restrict__ hi,
                              __nv_bfloat162* __restrict__ lo)
{
    int i = blockIdx.x * blockDim.x + threadIdx.x;
    if (i >= XPITCH * DINNER / 4) return;
    int row = i >> 9;
    int col4 = (i & 511) << 2;
    float f[4] = {0.f, 0.f, 0.f, 0.f};
    if (row < 96) {
        float4 v = *(const float4*)(in + (size_t)row * DINNER + col4);
        f[0] = v.x; f[1] = v.y; f[2] = v.z; f[3] = v.w;
    }
    __nv_bfloat16 h[4], l[4];
#pragma unroll
    for (int j = 0; j < 4; j++) {
        h[j] = __float2bfloat16(f[j]);
        l[j] = __float2bfloat16(f[j] - __bfloat162float(h[j]));
    }
    hi[2 * i]     = __nv_bfloat162(h[0], h[1]);
    hi[2 * i + 1] = __nv_bfloat162(h[2], h[3]);
    lo[2 * i]     = __nv_bfloat162(l[0], l[1]);
    lo[2 * i + 1] = __nv_bfloat162(l[2], l[3]);
}

// -------------------- causal conv1d + SiLU + z gate (+ inline split) -------
__global__ void conv_silu_kernel(const float* __restrict__ Wc,   // [DINNER,4]
                                 const float* __restrict__ bc)   // [DINNER]
{
    int i = blockIdx.x * blockDim.x + threadIdx.x;      // over MROWS*DINNER
    if (i >= MROWS * DINNER) return;
    int d = i & (DINNER - 1);
    int m = i >> 11;                                    // b*SEQ + l
    int b = m >> 10;
    int l = m & (SEQ - 1);

    float acc = bc[d];
#pragma unroll
    for (int k = 0; k < DCONV; k++) {
        int lt = l - (DCONV - 1) + k;
        if (lt >= 0)
            acc = fmaf(Wc[d * DCONV + k],
                       g_xz[(size_t)((b << 10) + lt) * (2 * DINNER) + d], acc);
    }
    float xc = acc / (1.f + __expf(-acc));              // silu
    g_xconv[i] = xc;
    __nv_bfloat16 hb = __float2bfloat16(xc);
    g_xch[i] = hb;
    g_xcl[i] = __float2bfloat16(xc - __bfloat162float(hb));

    float zv = g_xz[(size_t)m * (2 * DINNER) + DINNER + d];
    g_zsilu[i] = zv / (1.f + __expf(-zv));
}

// ---------------------------------------------------------------------------
// Selective scan v2 — smem-staged, cp.async double-buffered.
// 256 CTAs x 256 threads. CTA owns 16 channels x 16 states.
// ---------------------------------------------------------------------------
#define SCH 16
#define STT 64
#define NSTAGE (SEQ / STT)   // 16
#define BCP 36               // padded B/C row (floats); 144 B = 9*16 (aligned)

__global__ __launch_bounds__(256)
void scan_kernel(const float* __restrict__ A_log,   // [DINNER,16]
                 const float* __restrict__ Dp)      // [DINNER]
{
    __shared__ alignas(16) float s_dt[2][SCH][STT];
    __shared__ alignas(16) float s_xc[2][SCH][STT];
    __shared__ alignas(16) float s_zs[2][SCH][STT];
    __shared__ alignas(16) float s_bc[2][STT][BCP];

    const int tid = threadIdx.x;
    const int c = tid >> 4;              // channel within CTA (0..15)
    const int n = tid & 15;              // state
    const int chg = blockIdx.x * SCH;    // global channel base (0..4095)
    const int b  = chg >> 11;
    const int d0 = chg & (DINNER - 1);
    const size_t mb = (size_t)b * SEQ;

    const float A  = -__expf(A_log[(d0 + c) * DSTATE + n]);
    const float Dv = Dp[d0 + c];

    const uint32_t u_dt = smem_u32(s_dt), u_xc = smem_u32(s_xc);
    const uint32_t u_zs = smem_u32(s_zs), u_bc = smem_u32(s_bc);

    auto fill = [&](int s, int t0) {
#pragma unroll
        for (int i = 0; i < 4; i++) {
            int idx = i * 256 + tid;
            int ch = idx >> 6, t = idx & 63;
            size_t g = (mb + t0 + t) * DINNER + d0 + ch;
            uint32_t so = (uint32_t)(((s * SCH + ch) * STT + t) * 4);
            CPA4(u_dt + so, g_dt + g);
            CPA4(u_xc + so, g_xconv + g);
            CPA4(u_zs + so, g_zsilu + g);
        }
#pragma unroll
        for (int i = 0; i < 2; i++) {
            int idx = i * 256 + tid;
            int t = idx >> 3, chk = idx & 7;
            const float* src = g_xdbl + (mb + t0 + t) * XPITCH + DTRANK + chk * 4;
            uint32_t dst = u_bc + (uint32_t)(((s * STT + t) * BCP + chk * 4) * 4);
            CPA16(dst, src);
        }
        CP_COMMIT();
    };

    fill(0, 0);
    float h = 0.f;

    for (int st = 0; st < NSTAGE; st++) {
        const int cur = st & 1;
        if (st + 1 < NSTAGE) {
            fill(cur ^ 1, (st + 1) * STT);
            asm volatile("cp.async.wait_group 1;" ::: "memory");
        } else {
            asm volatile("cp.async.wait_group 0;" ::: "memory");
        }
        __syncthreads();

        const int t0 = st * STT;
#pragma unroll 4
        for (int t = 0; t < STT; t++) {
            float dtv = s_dt[cur][c][t];
            float xv  = s_xc[cur][c][t];
            float Bv  = s_bc[cur][t][n];
            float Cv  = s_bc[cur][t][16 + n];
            h = __expf(dtv * A) * h + dtv * Bv * xv;
            float yv = h * Cv;
            yv += __shfl_xor_sync(0xffffffffu, yv, 1);
            yv += __shfl_xor_sync(0xffffffffu, yv, 2);
            yv += __shfl_xor_sync(0xffffffffu, yv, 4);
            yv += __shfl_xor_sync(0xffffffffu, yv, 8);
            if (n == 0) {
                float yo = (yv + xv * Dv) * s_zs[cur][c][t];
                __nv_bfloat16 hb = __float2bfloat16(yo);
                __nv_bfloat16 lb = __float2bfloat16(yo - __bfloat162float(hb));
                size_t o = (mb + t0 + t) * DINNER + d0 + c;
                g_yh[o] = hb;
                g_yl[o] = lb;
            }
        }
        __syncthreads();
    }
}

// -------------------- host launcher ----------------------------------------
extern "C" void kernel_launch(void* const* d_in, const int* in_sizes, int n_in,
                              void* d_out, int out_size)
{
    const float* x      = (const float*)d_in[0];
    const float* W_in   = (const float*)d_in[1];
    const float* W_conv = (const float*)d_in[2];
    const float* b_conv = (const float*)d_in[3];
    const float* W_x    = (const float*)d_in[4];
    const float* W_dt   = (const float*)d_in[5];
    const float* b_dt   = (const float*)d_in[6];
    const float* A_log  = (const float*)d_in[7];
    const float* Dp     = (const float*)d_in[8];
    const float* W_out  = (const float*)d_in[9];
    float* out = (float*)d_out;

    float *p_xz, *p_xdbl, *p_dt;
    cudaGetSymbolAddress((void**)&p_xz,   g_xz);
    cudaGetSymbolAddress((void**)&p_xdbl, g_xdbl);
    cudaGetSymbolAddress((void**)&p_dt,   g_dt);

    __nv_bfloat16 *xhi, *xlo, *Wih, *Wil, *xch, *xcl, *Wxh, *Wxl;
    __nv_bfloat16 *xdh, *xdl, *Wdh, *Wdl, *yh, *yl, *Woh, *Wol;
    cudaGetSymbolAddress((void**)&xhi, g_xhi); cudaGetSymbolAddress((void**)&xlo, g_xlo);
    cudaGetSymbolAddress((void**)&Wih, g_Wih); cudaGetSymbolAddress((void**)&Wil, g_Wil);
    cudaGetSymbolAddress((void**)&xch, g_xch); cudaGetSymbolAddress((void**)&xcl, g_xcl);
    cudaGetSymbolAddress((void**)&Wxh, g_Wxh); cudaGetSymbolAddress((void**)&Wxl, g_Wxl);
    cudaGetSymbolAddress((void**)&xdh, g_xdh); cudaGetSymbolAddress((void**)&xdl, g_xdl);
    cudaGetSymbolAddress((void**)&Wdh, g_Wdh); cudaGetSymbolAddress((void**)&Wdl, g_Wdl);
    cudaGetSymbolAddress((void**)&yh,  g_yh);  cudaGetSymbolAddress((void**)&yl,  g_yl);
    cudaGetSymbolAddress((void**)&Woh, g_Woh); cudaGetSymbolAddress((void**)&Wol, g_Wol);

    cudaFuncSetAttribute(gemm_mma<0>, cudaFuncAttributeMaxDynamicSharedMemorySize, GSMEM);
    cudaFuncSetAttribute(gemm_mma<1>, cudaFuncAttributeMaxDynamicSharedMemorySize, GSMEM);
    cudaFuncSetAttribute(gemm_mma<2>, cudaFuncAttributeMaxDynamicSharedMemorySize, GSMEM);

    const int CT = 256;
    #define CVT(src, dh, dl, n) \
        cvt_hl<<<((n) / 4 + CT - 1) / CT, CT>>>((const float4*)(src), \
            (__nv_bfloat162*)(dh), (__nv_bfloat162*)(dl), (n) / 4)

    // splits needed by GEMM1 (+pad)
    CVT(x,     xhi, xlo, MROWS * DMODEL);
    CVT(W_in,  Wih, Wil, 2 * DINNER * DMODEL);
    cvt_hl_pad_wx<<<(XPITCH * DINNER / 4 + CT - 1) / CT, CT>>>(
        W_x, (__nv_bfloat162*)Wxh, (__nv_bfloat162*)Wxl);

    // 3) xz = x @ W_in^T   [2048, 4096], K=1024
    {
        dim3 grid((2 * DINNER) / BNT, MROWS / BMT, 1);   // 32 x 16
        gemm_mma<0><<<grid, 256, GSMEM>>>(xhi, xlo, DMODEL, Wih, Wil, DMODEL,
                                          nullptr, p_xz, 2 * DINNER, DMODEL);
    }
    // remaining weight splits + xdbl zero (independent of GEMM1)
    CVT(W_dt,  Wdh, Wdl, DINNER * DTRANK);
    CVT(W_out, Woh, Wol, DMODEL * DINNER);
    zero_xdbl<<<(MROWS * XPITCH / 4 + CT - 1) / CT, CT>>>();

    // causal conv + silu + z gate (+ xconv hi/lo split fused)
    conv_silu_kernel<<<(MROWS * DINNER + CT - 1) / CT, CT>>>(W_conv, b_conv);

    // x_dbl = x_conv @ W_x^T   [2048, 128(pad)], K=2048, split-K=8 (atomics)
    {
        dim3 grid(XPITCH / BNT, MROWS / BMT, 8);         // 1 x 16 x 8
        gemm_mma<2><<<grid, 256, GSMEM>>>(xch, xcl, DINNER, Wxh, Wxl, DINNER,
                                          nullptr, p_xdbl, XPITCH, DINNER / 8);
    }
    CVT(p_xdbl, xdh, xdl, MROWS * XPITCH);

    // dt = softplus(x_dbl[:, :64] @ W_dt^T + b_dt)   [2048, 2048], K=64
    {
        dim3 grid(DINNER / BNT, MROWS / BMT, 1);         // 16 x 16
        gemm_mma<1><<<grid, 256, GSMEM>>>(xdh, xdl, XPITCH, Wdh, Wdl, DTRANK,
                                          b_dt, p_dt, DINNER, DTRANK);
    }
    // selective scan (+ skip + gate fused, emits bf16 hi/lo directly)
    scan_kernel<<<BATCH * DINNER / SCH, 256>>>(A_log, Dp);

    // out = gated @ W_out^T   [2048, 1024], K=2048
    {
        dim3 grid(DMODEL / BNT, MROWS / BMT, 1);         // 8 x 16
        gemm_mma<0><<<grid, 256, GSMEM>>>(yh, yl, DINNER, Woh, Wol, DINNER,
                                          nullptr, out, DMODEL, DINNER);
    }
    (void)in_sizes; (void)n_in; (void)out_size;
}